// round 1
// baseline (speedup 1.0000x reference)
#include <cuda_runtime.h>
#include <cstddef>

#define B_   256
#define S_   128
#define IN_  64
#define H_   512
#define W_   512
#define G4   2048   // 4*H
#define KC   576    // IN + H (encoder concat K)
#define NDEC 2560   // G4 + W  (combined decoder GEMM width)

// ---------------- scratch (device globals: allocation-free rule) ----------------
__device__ float g_Wc_enc[G4 * KC];      // permuted [q=4j+g][k]  (k<64 from W_ih, else W_hh)
__device__ float g_bc_enc[G4];           // b_ih + b_hh, permuted
__device__ float g_Mdec[NDEC * H_];      // rows q<2048: permuted W_hh_dec; rows>=2048: W2
__device__ float g_xproj[B_ * G4];       // decoder_input @ W_ih_dec^T + biases, permuted
__device__ float g_hA[B_ * H_];
__device__ float g_hB[B_ * H_];
__device__ float g_c[B_ * H_];           // encoder cell; after encoder == c_last (decoder keeps it fixed)
__device__ float g_hdec[B_ * H_];
__device__ float g_enc_outs[(size_t)S_ * B_ * H_];   // [s][b][h]
__device__ float g_enc_proj[(size_t)S_ * B_ * W_];   // [s][b][w]
__device__ float g_decout[B_ * NDEC];    // per-step combined GEMM out: gates(2048) | hw2(512)

// ---------------- helpers ----------------
__device__ __forceinline__ float sigf(float x) { return 1.0f / (1.0f + __expf(-x)); }
__device__ __forceinline__ float fast_tanh(float x) {
    float y; asm("tanh.approx.f32 %0, %1;" : "=f"(y) : "f"(x)); return y;
}

// ---------------- prep kernels ----------------
__global__ void k_prep_encW(const float* __restrict__ Wih, const float* __restrict__ Whh,
                            const float* __restrict__ bih, const float* __restrict__ bhh) {
    int q = blockIdx.x;          // 0..2047
    int k = threadIdx.x;         // 0..575
    int j = q >> 2, g = q & 3;
    int r = g * H_ + j;
    float v = (k < IN_) ? Wih[r * IN_ + k] : Whh[r * H_ + (k - IN_)];
    g_Wc_enc[q * KC + k] = v;
    if (k == 0) g_bc_enc[q] = bih[r] + bhh[r];
}

__global__ void k_prep_decW(const float* __restrict__ Whh, const float* __restrict__ W2) {
    int q = blockIdx.x;          // 0..2559
    int k = threadIdx.x;         // 0..511
    float v;
    if (q < G4) {
        int j = q >> 2, g = q & 3;
        int r = g * H_ + j;
        v = Whh[r * H_ + k];
    } else {
        v = W2[(q - G4) * H_ + k];
    }
    g_Mdec[q * H_ + k] = v;
}

__global__ void k_xproj(const float* __restrict__ di, const float* __restrict__ Wih,
                        const float* __restrict__ bih, const float* __restrict__ bhh) {
    int idx = blockIdx.x * blockDim.x + threadIdx.x;   // B_*G4
    if (idx >= B_ * G4) return;
    int b = idx >> 11, q = idx & (G4 - 1);
    int j = q >> 2, g = q & 3;
    int r = g * H_ + j;
    float s = bih[r] + bhh[r];
    const float* wr = &Wih[r * IN_];
    const float* xr = &di[b * IN_];
    #pragma unroll
    for (int k = 0; k < IN_; k++) s += xr[k] * wr[k];
    g_xproj[idx] = s;
}

__global__ void k_zero() {
    int idx = blockIdx.x * blockDim.x + threadIdx.x;   // B_*H_
    if (idx < B_ * H_) { g_hA[idx] = 0.0f; g_c[idx] = 0.0f; }
}

// ---------------- generic SGEMM: C[M,N] = A[M,K] * B[N,K]^T ----------------
__global__ __launch_bounds__(256)
void sgemm_nt(const float* __restrict__ A, const float* __restrict__ Bm,
              float* __restrict__ C, int K, int lda, int ldb, int ldc) {
    __shared__ float As[64][68];
    __shared__ float Bs[64][68];
    int tid = threadIdx.x;
    int tx = tid & 15, ty = tid >> 4;
    int m0 = blockIdx.y * 64, n0 = blockIdx.x * 64;
    int arow = tid >> 4;
    int acol = (tid & 15) * 4;
    float acc[4][4] = {};
    for (int k0 = 0; k0 < K; k0 += 64) {
        #pragma unroll
        for (int i = 0; i < 4; i++) {
            int r = arow + i * 16;
            float4 av = *(const float4*)&A[(size_t)(m0 + r) * lda + k0 + acol];
            As[acol + 0][r] = av.x; As[acol + 1][r] = av.y;
            As[acol + 2][r] = av.z; As[acol + 3][r] = av.w;
            float4 bv = *(const float4*)&Bm[(size_t)(n0 + r) * ldb + k0 + acol];
            Bs[acol + 0][r] = bv.x; Bs[acol + 1][r] = bv.y;
            Bs[acol + 2][r] = bv.z; Bs[acol + 3][r] = bv.w;
        }
        __syncthreads();
        #pragma unroll
        for (int kk = 0; kk < 64; kk++) {
            float ar[4], br[4];
            *(float4*)ar = *(const float4*)&As[kk][ty * 4];
            *(float4*)br = *(const float4*)&Bs[kk][tx * 4];
            #pragma unroll
            for (int i = 0; i < 4; i++)
                #pragma unroll
                for (int j = 0; j < 4; j++)
                    acc[i][j] += ar[i] * br[j];
        }
        __syncthreads();
    }
    #pragma unroll
    for (int r = 0; r < 4; r++) {
        float4 o = make_float4(acc[r][0], acc[r][1], acc[r][2], acc[r][3]);
        *(float4*)&C[(size_t)(m0 + ty * 4 + r) * ldc + n0 + tx * 4] = o;
    }
}

// ---------------- encoder step: fused GEMM + LSTM epilogue ----------------
__global__ __launch_bounds__(256)
void enc_step(const float* __restrict__ x, int t,
              const float* __restrict__ hin, float* __restrict__ hout) {
    __shared__ float As[64][68];
    __shared__ float Bs[64][68];
    int tid = threadIdx.x;
    int tx = tid & 15, ty = tid >> 4;
    int m0 = blockIdx.y * 64, n0 = blockIdx.x * 64;
    int arow = tid >> 4;
    int acol = (tid & 15) * 4;
    float acc[4][4] = {};
    for (int k0 = 0; k0 < KC; k0 += 64) {
        #pragma unroll
        for (int i = 0; i < 4; i++) {
            int r = arow + i * 16;
            int gk = k0 + acol;
            float4 av;
            if (gk < IN_) av = *(const float4*)&x[((size_t)(m0 + r) * S_ + t) * IN_ + gk];
            else          av = *(const float4*)&hin[(size_t)(m0 + r) * H_ + (gk - IN_)];
            As[acol + 0][r] = av.x; As[acol + 1][r] = av.y;
            As[acol + 2][r] = av.z; As[acol + 3][r] = av.w;
            float4 bv = *(const float4*)&g_Wc_enc[(size_t)(n0 + r) * KC + gk];
            Bs[acol + 0][r] = bv.x; Bs[acol + 1][r] = bv.y;
            Bs[acol + 2][r] = bv.z; Bs[acol + 3][r] = bv.w;
        }
        __syncthreads();
        #pragma unroll
        for (int kk = 0; kk < 64; kk++) {
            float ar[4], br[4];
            *(float4*)ar = *(const float4*)&As[kk][ty * 4];
            *(float4*)br = *(const float4*)&Bs[kk][tx * 4];
            #pragma unroll
            for (int i = 0; i < 4; i++)
                #pragma unroll
                for (int j = 0; j < 4; j++)
                    acc[i][j] += ar[i] * br[j];
        }
        __syncthreads();
    }
    // LSTM epilogue: each thread's 4 cols form one complete (i,f,g,o) quad
    int q0 = n0 + tx * 4;
    int j  = q0 >> 2;
    float bi = g_bc_enc[q0], bf = g_bc_enc[q0 + 1], bg = g_bc_enc[q0 + 2], bo = g_bc_enc[q0 + 3];
    #pragma unroll
    for (int r = 0; r < 4; r++) {
        int b = m0 + ty * 4 + r;
        float i_ = sigf(acc[r][0] + bi);
        float f_ = sigf(acc[r][1] + bf);
        float gg = tanhf(acc[r][2] + bg);
        float o_ = sigf(acc[r][3] + bo);
        float cn = f_ * g_c[b * H_ + j] + i_ * gg;
        g_c[b * H_ + j] = cn;
        float hn = o_ * tanhf(cn);
        hout[b * H_ + j] = hn;
        g_enc_outs[((size_t)t * B_ + b) * H_ + j] = hn;
    }
}

// ---------------- decoder LSTM cell (cell state fixed at c_last) ----------------
__global__ void dec_cell() {
    int idx = blockIdx.x * blockDim.x + threadIdx.x;   // B_*H_
    if (idx >= B_ * H_) return;
    int b = idx >> 9, j = idx & (H_ - 1);
    float4 gr = *(const float4*)&g_decout[(size_t)b * NDEC + 4 * j];
    float4 xp = *(const float4*)&g_xproj[(size_t)b * G4 + 4 * j];
    float i_ = sigf(gr.x + xp.x);
    float f_ = sigf(gr.y + xp.y);
    float gg = tanhf(gr.z + xp.z);
    float o_ = sigf(gr.w + xp.w);
    float cn = f_ * g_c[idx] + i_ * gg;     // c NOT updated (faithful to reference)
    g_hdec[idx] = o_ * tanhf(cn);
}

// ---------------- fused attention + log_softmax (one block per batch row) ----------------
__global__ __launch_bounds__(512)
void attn_softmax(int t, const float* __restrict__ vt, float* __restrict__ out) {
    __shared__ float hw2s[W_];
    __shared__ float vts[W_];
    __shared__ float sc[S_];
    __shared__ float lse_s;
    int b = blockIdx.x;
    int tid = threadIdx.x;
    hw2s[tid] = g_decout[(size_t)b * NDEC + G4 + tid];
    vts[tid]  = vt[tid];
    __syncthreads();
    int w = tid >> 5, l = tid & 31;
    for (int s8 = 0; s8 < 8; s8++) {
        int s = s8 * 16 + w;
        const float* ep = &g_enc_proj[((size_t)s * B_ + b) * W_];
        float acc = 0.0f;
        #pragma unroll
        for (int r = 0; r < 4; r++) {
            int i0 = r * 128 + l * 4;
            float4 e  = *(const float4*)&ep[i0];
            float4 hv = *(const float4*)&hw2s[i0];
            float4 vv = *(const float4*)&vts[i0];
            acc += fast_tanh(e.x + hv.x) * vv.x;
            acc += fast_tanh(e.y + hv.y) * vv.y;
            acc += fast_tanh(e.z + hv.z) * vv.z;
            acc += fast_tanh(e.w + hv.w) * vv.w;
        }
        #pragma unroll
        for (int off = 16; off; off >>= 1) acc += __shfl_xor_sync(0xFFFFFFFFu, acc, off);
        if (l == 0) sc[s] = acc;
    }
    __syncthreads();
    if (w == 0) {
        float4 v = *(const float4*)&sc[l * 4];
        float m = fmaxf(fmaxf(v.x, v.y), fmaxf(v.z, v.w));
        #pragma unroll
        for (int off = 16; off; off >>= 1) m = fmaxf(m, __shfl_xor_sync(0xFFFFFFFFu, m, off));
        float e = __expf(v.x - m) + __expf(v.y - m) + __expf(v.z - m) + __expf(v.w - m);
        #pragma unroll
        for (int off = 16; off; off >>= 1) e += __shfl_xor_sync(0xFFFFFFFFu, e, off);
        if (l == 0) lse_s = m + logf(e);
    }
    __syncthreads();
    float L = lse_s;
    if (tid < S_) out[((size_t)b * S_ + t) * S_ + tid] = sc[tid] - L;
}

// ---------------- launch ----------------
extern "C" void kernel_launch(void* const* d_in, const int* in_sizes, int n_in,
                              void* d_out, int out_size) {
    const float* x        = (const float*)d_in[0];
    const float* dec_in   = (const float*)d_in[1];
    const float* W_ih_enc = (const float*)d_in[2];
    const float* W_hh_enc = (const float*)d_in[3];
    const float* b_ih_enc = (const float*)d_in[4];
    const float* b_hh_enc = (const float*)d_in[5];
    const float* W_ih_dec = (const float*)d_in[6];
    const float* W_hh_dec = (const float*)d_in[7];
    const float* b_ih_dec = (const float*)d_in[8];
    const float* b_hh_dec = (const float*)d_in[9];
    const float* W1       = (const float*)d_in[10];
    const float* W2       = (const float*)d_in[11];
    const float* vt       = (const float*)d_in[12];
    float* out = (float*)d_out;

    float *p_hA, *p_hB, *p_hdec, *p_encouts, *p_encproj, *p_decout, *p_Mdec;
    cudaGetSymbolAddress((void**)&p_hA,      g_hA);
    cudaGetSymbolAddress((void**)&p_hB,      g_hB);
    cudaGetSymbolAddress((void**)&p_hdec,    g_hdec);
    cudaGetSymbolAddress((void**)&p_encouts, g_enc_outs);
    cudaGetSymbolAddress((void**)&p_encproj, g_enc_proj);
    cudaGetSymbolAddress((void**)&p_decout,  g_decout);
    cudaGetSymbolAddress((void**)&p_Mdec,    g_Mdec);

    // prep
    k_prep_encW<<<G4, KC>>>(W_ih_enc, W_hh_enc, b_ih_enc, b_hh_enc);
    k_prep_decW<<<NDEC, H_>>>(W_hh_dec, W2);
    k_xproj<<<(B_ * G4 + 255) / 256, 256>>>(dec_in, W_ih_dec, b_ih_dec, b_hh_dec);
    k_zero<<<(B_ * H_ + 255) / 256, 256>>>();

    // encoder: 128 sequential fused GEMM+LSTM steps (h double-buffered)
    for (int t = 0; t < S_; t++) {
        const float* hin = (t & 1) ? p_hB : p_hA;
        float*       hout = (t & 1) ? p_hA : p_hB;
        enc_step<<<dim3(G4 / 64, B_ / 64), 256>>>(x, t, hin, hout);
    }
    // h_last ends in g_hA (128 steps), c_last in g_c

    // enc_proj = enc_outs @ W1^T   [S*B, W]
    sgemm_nt<<<dim3(W_ / 64, (S_ * B_) / 64), 256>>>(p_encouts, W1, p_encproj,
                                                     H_, H_, H_, W_);

    // prime decoder: gates_raw = h_last @ Mdec^T (hw2 part unused this once)
    sgemm_nt<<<dim3(NDEC / 64, B_ / 64), 256>>>(p_hA, p_Mdec, p_decout,
                                                H_, H_, H_, NDEC);

    // decoder loop
    for (int t = 0; t < S_; t++) {
        dec_cell<<<(B_ * H_ + 255) / 256, 256>>>();
        sgemm_nt<<<dim3(NDEC / 64, B_ / 64), 256>>>(p_hdec, p_Mdec, p_decout,
                                                    H_, H_, H_, NDEC);
        attn_softmax<<<B_, 512>>>(t, vt, out);
    }

    (void)in_sizes; (void)n_in; (void)out_size;
}

// round 2
// speedup vs baseline: 1.8289x; 1.8289x over previous
#include <cuda_runtime.h>
#include <cstdint>
#include <cstddef>

#define B_   256
#define S_   128
#define IN_  64
#define H_   512
#define W_   512
#define G4   2048   // 4*H
#define NDEC 2560   // G4 + W (combined decoder GEMM width)

// ---------------- scratch (device globals: allocation-free rule) ----------------
__device__ float g_Wih_p[G4 * IN_];                 // quad-permuted, tf32-rounded
__device__ float g_Whh_p[G4 * H_];                  // quad-permuted, tf32-rounded
__device__ float g_bc_enc[G4];                      // b_ih + b_hh, permuted (fp32)
__device__ float g_Mdec[NDEC * H_];                 // rows<2048: permuted W_hh_dec; rest: W2 (tf32-rounded)
__device__ float g_W1r[W_ * H_];                    // tf32-rounded W1
__device__ float g_xproj[B_ * G4];                  // dec_input@W_ih_dec^T + biases (permuted)
__device__ float g_xall[(size_t)B_ * S_ * G4];      // x@W_ih_enc^T + biases, rows b*S+t
__device__ float g_hA[B_ * H_];
__device__ float g_hB[B_ * H_];
__device__ float g_c[B_ * H_];                      // encoder cell; fixed c_last in decoder
__device__ float g_hd0[B_ * H_];
__device__ float g_hd1[B_ * H_];
__device__ float g_hw2[B_ * W_];                    // h@W2^T for attention
__device__ float g_enc_outs[(size_t)S_ * B_ * H_];  // rows t*B+b
__device__ float g_enc_proj[(size_t)S_ * B_ * W_];  // rows s*B+b

// ---------------- helpers ----------------
__device__ __forceinline__ float sigf(float x) { return 1.0f / (1.0f + __expf(-x)); }
__device__ __forceinline__ float fast_tanh(float x) {
    float y; asm("tanh.approx.f32 %0, %1;" : "=f"(y) : "f"(x)); return y;
}
__device__ __forceinline__ uint32_t tf32r(float x) {
    uint32_t u; asm("cvt.rna.tf32.f32 %0, %1;" : "=r"(u) : "f"(x)); return u;
}
__device__ __forceinline__ void mma8(float* d, const uint32_t* a, const uint32_t* b) {
    asm volatile("mma.sync.aligned.m16n8k8.row.col.f32.tf32.tf32.f32 "
        "{%0,%1,%2,%3}, {%4,%5,%6,%7}, {%8,%9}, {%0,%1,%2,%3};"
        : "+f"(d[0]), "+f"(d[1]), "+f"(d[2]), "+f"(d[3])
        : "r"(a[0]), "r"(a[1]), "r"(a[2]), "r"(a[3]), "r"(b[0]), "r"(b[1]));
}

// ---------------- prep kernels ----------------
__global__ void k_prep_enc(const float* __restrict__ Wih, const float* __restrict__ Whh,
                           const float* __restrict__ bih, const float* __restrict__ bhh) {
    int q = blockIdx.x, k = threadIdx.x;            // q<2048, k<512
    int j = q >> 2, g = q & 3;
    int r = g * H_ + j;
    g_Whh_p[q * H_ + k] = __uint_as_float(tf32r(Whh[r * H_ + k]));
    if (k < IN_) g_Wih_p[q * IN_ + k] = __uint_as_float(tf32r(Wih[r * IN_ + k]));
    if (k == 0)  g_bc_enc[q] = bih[r] + bhh[r];
}
__global__ void k_prep_dec(const float* __restrict__ Whh, const float* __restrict__ W2) {
    int q = blockIdx.x, k = threadIdx.x;            // q<2560, k<512
    float v;
    if (q < G4) { int j = q >> 2, g = q & 3; v = Whh[(g * H_ + j) * H_ + k]; }
    else        { v = W2[(q - G4) * H_ + k]; }
    g_Mdec[q * H_ + k] = __uint_as_float(tf32r(v));
}
__global__ void k_prep_W1(const float* __restrict__ W1) {
    int n = blockIdx.x, k = threadIdx.x;
    g_W1r[n * H_ + k] = __uint_as_float(tf32r(W1[n * H_ + k]));
}
__global__ void k_xproj(const float* __restrict__ di, const float* __restrict__ Wih,
                        const float* __restrict__ bih, const float* __restrict__ bhh) {
    int idx = blockIdx.x * blockDim.x + threadIdx.x;   // B_*G4
    if (idx >= B_ * G4) return;
    int b = idx >> 11, q = idx & (G4 - 1);
    int j = q >> 2, g = q & 3;
    int r = g * H_ + j;
    float s = bih[r] + bhh[r];
    const float* wr = &Wih[r * IN_];
    const float* xr = &di[b * IN_];
    #pragma unroll
    for (int k = 0; k < IN_; k++) s += xr[k] * wr[k];
    g_xproj[idx] = s;
}
__global__ void k_zero() {
    int idx = blockIdx.x * blockDim.x + threadIdx.x;
    if (idx < B_ * H_) { g_hA[idx] = 0.0f; g_c[idx] = 0.0f; }
}

// ---------------- tf32 tensor-core GEMM: C[M,N] = A[M,K] * Bw[N,K]^T ----------------
// MODE 0: plain store to C
// MODE 1: store + g_bc_enc bias (xall)
// MODE 2: encoder fused LSTM epilogue (C = hout; uses g_xall[t], g_c, g_enc_outs)
// MODE 3: decoder fused cell epilogue (cols<2048 -> h to C; cols>=2048 -> raw to g_hw2)
template<int MODE>
__global__ __launch_bounds__(128)
void gemm_tf32(const float* __restrict__ A, int lda,
               const float* __restrict__ Bw, int ldb,
               float* __restrict__ C, int ldc, int K, int t)
{
    __shared__ float As[64][36];
    __shared__ float Bs[64][36];
    int tid = threadIdx.x, lane = tid & 31, warp = tid >> 5;
    int wm = warp >> 1, wn = warp & 1;            // warp grid 2x2, warp tile 32x32
    int gid = lane >> 2, tig = lane & 3;
    int m0 = blockIdx.y * 64, n0 = blockIdx.x * 64;

    float acc[2][4][4];
    #pragma unroll
    for (int a = 0; a < 2; a++)
        #pragma unroll
        for (int b = 0; b < 4; b++)
            #pragma unroll
            for (int c = 0; c < 4; c++) acc[a][b][c] = 0.0f;

    float4 ra[4], rb[4];
    int lrow[4], lc4[4];
    #pragma unroll
    for (int i = 0; i < 4; i++) { int idx = tid + i * 128; lrow[i] = idx >> 3; lc4[i] = (idx & 7) * 4; }

    // prologue load chunk 0
    #pragma unroll
    for (int i = 0; i < 4; i++) {
        ra[i] = *(const float4*)&A [(size_t)(m0 + lrow[i]) * lda + lc4[i]];
        rb[i] = *(const float4*)&Bw[(size_t)(n0 + lrow[i]) * ldb + lc4[i]];
    }
    #pragma unroll
    for (int i = 0; i < 4; i++) {
        float4 va;
        va.x = __uint_as_float(tf32r(ra[i].x)); va.y = __uint_as_float(tf32r(ra[i].y));
        va.z = __uint_as_float(tf32r(ra[i].z)); va.w = __uint_as_float(tf32r(ra[i].w));
        *(float4*)&As[lrow[i]][lc4[i]] = va;
        *(float4*)&Bs[lrow[i]][lc4[i]] = rb[i];
    }
    __syncthreads();

    int nIt = K >> 5;
    for (int it = 0; it < nIt; it++) {
        if (it + 1 < nIt) {
            int k0 = (it + 1) << 5;
            #pragma unroll
            for (int i = 0; i < 4; i++) {
                ra[i] = *(const float4*)&A [(size_t)(m0 + lrow[i]) * lda + k0 + lc4[i]];
                rb[i] = *(const float4*)&Bw[(size_t)(n0 + lrow[i]) * ldb + k0 + lc4[i]];
            }
        }
        // compute 4 k8 micro-steps from smem
        #pragma unroll
        for (int k8 = 0; k8 < 4; k8++) {
            int kc = k8 * 8;
            uint32_t af[2][4], bf[4][2];
            #pragma unroll
            for (int mt = 0; mt < 2; mt++) {
                int r = wm * 32 + mt * 16 + gid;
                af[mt][0] = __float_as_uint(As[r    ][kc + tig]);
                af[mt][1] = __float_as_uint(As[r + 8][kc + tig]);
                af[mt][2] = __float_as_uint(As[r    ][kc + tig + 4]);
                af[mt][3] = __float_as_uint(As[r + 8][kc + tig + 4]);
            }
            #pragma unroll
            for (int nt = 0; nt < 4; nt++) {
                int n = wn * 32 + nt * 8 + gid;
                bf[nt][0] = __float_as_uint(Bs[n][kc + tig]);
                bf[nt][1] = __float_as_uint(Bs[n][kc + tig + 4]);
            }
            #pragma unroll
            for (int mt = 0; mt < 2; mt++)
                #pragma unroll
                for (int nt = 0; nt < 4; nt++) mma8(acc[mt][nt], af[mt], bf[nt]);
        }
        __syncthreads();
        if (it + 1 < nIt) {
            #pragma unroll
            for (int i = 0; i < 4; i++) {
                float4 va;
                va.x = __uint_as_float(tf32r(ra[i].x)); va.y = __uint_as_float(tf32r(ra[i].y));
                va.z = __uint_as_float(tf32r(ra[i].z)); va.w = __uint_as_float(tf32r(ra[i].w));
                *(float4*)&As[lrow[i]][lc4[i]] = va;
                *(float4*)&Bs[lrow[i]][lc4[i]] = rb[i];
            }
            __syncthreads();
        }
    }

    // ------------- epilogue -------------
    #pragma unroll
    for (int mt = 0; mt < 2; mt++) {
        #pragma unroll
        for (int nt = 0; nt < 4; nt++) {
            float c0 = acc[mt][nt][0], c1 = acc[mt][nt][1], c2 = acc[mt][nt][2], c3 = acc[mt][nt][3];
            int rr = m0 + wm * 32 + mt * 16 + gid;
            int cc = n0 + wn * 32 + nt * 8 + 2 * tig;
            if (MODE == 0) {
                *(float2*)&C[(size_t)rr * ldc + cc]       = make_float2(c0, c1);
                *(float2*)&C[(size_t)(rr + 8) * ldc + cc] = make_float2(c2, c3);
            } else if (MODE == 1) {
                float b0 = g_bc_enc[cc], b1 = g_bc_enc[cc + 1];
                *(float2*)&C[(size_t)rr * ldc + cc]       = make_float2(c0 + b0, c1 + b1);
                *(float2*)&C[(size_t)(rr + 8) * ldc + cc] = make_float2(c2 + b0, c3 + b1);
            } else if (MODE == 3 && n0 >= G4) {
                *(float2*)&g_hw2[(size_t)rr * W_ + (cc - G4)]       = make_float2(c0, c1);
                *(float2*)&g_hw2[(size_t)(rr + 8) * W_ + (cc - G4)] = make_float2(c2, c3);
            } else {
                // fused LSTM gate epilogue (MODE 2, or MODE 3 gate columns)
                float x0 = __shfl_xor_sync(0xFFFFFFFFu, c0, 1);
                float x1 = __shfl_xor_sync(0xFFFFFFFFu, c1, 1);
                float x2 = __shfl_xor_sync(0xFFFFFFFFu, c2, 1);
                float x3 = __shfl_xor_sync(0xFFFFFFFFu, c3, 1);
                int p = tig & 1;
                int r = rr + (p ? 8 : 0);
                int j = ((n0 + wn * 32 + nt * 8) >> 2) + (tig >> 1);
                float gi = p ? x2 : c0;
                float gf = p ? x3 : c1;
                float gg = p ? c2 : x0;
                float go = p ? c3 : x1;
                float4 xa;
                if (MODE == 2) xa = *(const float4*)&g_xall[((size_t)r * S_ + t) * G4 + 4 * j];
                else           xa = *(const float4*)&g_xproj[(size_t)r * G4 + 4 * j];
                float i_ = sigf(gi + xa.x);
                float f_ = sigf(gf + xa.y);
                float g_ = tanhf(gg + xa.z);
                float o_ = sigf(go + xa.w);
                float cold = g_c[r * H_ + j];
                float cn = f_ * cold + i_ * g_;
                float h = o_ * tanhf(cn);
                if (MODE == 2) {
                    g_c[r * H_ + j] = cn;
                    C[(size_t)r * H_ + j] = h;                       // hout
                    g_enc_outs[((size_t)t * B_ + r) * H_ + j] = h;
                } else {
                    C[(size_t)r * H_ + j] = h;                       // next decoder hidden
                }
            }
        }
    }
}

// ---------------- fused attention + log_softmax (one block per batch row) ----------------
__global__ __launch_bounds__(512)
void attn_softmax(int t, const float* __restrict__ vt, float* __restrict__ out) {
    __shared__ float hw2s[W_];
    __shared__ float vts[W_];
    __shared__ float sc[S_];
    __shared__ float lse_s;
    int b = blockIdx.x;
    int tid = threadIdx.x;
    hw2s[tid] = g_hw2[(size_t)b * W_ + tid];
    vts[tid]  = vt[tid];
    __syncthreads();
    int w = tid >> 5, l = tid & 31;
    for (int s8 = 0; s8 < 8; s8++) {
        int s = s8 * 16 + w;
        const float* ep = &g_enc_proj[((size_t)s * B_ + b) * W_];
        float acc = 0.0f;
        #pragma unroll
        for (int r = 0; r < 4; r++) {
            int i0 = r * 128 + l * 4;
            float4 e  = *(const float4*)&ep[i0];
            float4 hv = *(const float4*)&hw2s[i0];
            float4 vv = *(const float4*)&vts[i0];
            acc += fast_tanh(e.x + hv.x) * vv.x;
            acc += fast_tanh(e.y + hv.y) * vv.y;
            acc += fast_tanh(e.z + hv.z) * vv.z;
            acc += fast_tanh(e.w + hv.w) * vv.w;
        }
        #pragma unroll
        for (int off = 16; off; off >>= 1) acc += __shfl_xor_sync(0xFFFFFFFFu, acc, off);
        if (l == 0) sc[s] = acc;
    }
    __syncthreads();
    if (w == 0) {
        float4 v = *(const float4*)&sc[l * 4];
        float m = fmaxf(fmaxf(v.x, v.y), fmaxf(v.z, v.w));
        #pragma unroll
        for (int off = 16; off; off >>= 1) m = fmaxf(m, __shfl_xor_sync(0xFFFFFFFFu, m, off));
        float e = __expf(v.x - m) + __expf(v.y - m) + __expf(v.z - m) + __expf(v.w - m);
        #pragma unroll
        for (int off = 16; off; off >>= 1) e += __shfl_xor_sync(0xFFFFFFFFu, e, off);
        if (l == 0) lse_s = m + logf(e);
    }
    __syncthreads();
    float L = lse_s;
    if (tid < S_) out[((size_t)b * S_ + t) * S_ + tid] = sc[tid] - L;
}

// ---------------- launch ----------------
extern "C" void kernel_launch(void* const* d_in, const int* in_sizes, int n_in,
                              void* d_out, int out_size) {
    const float* x        = (const float*)d_in[0];
    const float* dec_in   = (const float*)d_in[1];
    const float* W_ih_enc = (const float*)d_in[2];
    const float* W_hh_enc = (const float*)d_in[3];
    const float* b_ih_enc = (const float*)d_in[4];
    const float* b_hh_enc = (const float*)d_in[5];
    const float* W_ih_dec = (const float*)d_in[6];
    const float* W_hh_dec = (const float*)d_in[7];
    const float* b_ih_dec = (const float*)d_in[8];
    const float* b_hh_dec = (const float*)d_in[9];
    const float* W1       = (const float*)d_in[10];
    const float* W2       = (const float*)d_in[11];
    const float* vt       = (const float*)d_in[12];
    float* out = (float*)d_out;

    float *p_hA, *p_hB, *p_hd0, *p_hd1, *p_encouts, *p_encproj, *p_Mdec,
          *p_Wih, *p_Whh, *p_W1r, *p_xall;
    cudaGetSymbolAddress((void**)&p_hA,      g_hA);
    cudaGetSymbolAddress((void**)&p_hB,      g_hB);
    cudaGetSymbolAddress((void**)&p_hd0,     g_hd0);
    cudaGetSymbolAddress((void**)&p_hd1,     g_hd1);
    cudaGetSymbolAddress((void**)&p_encouts, g_enc_outs);
    cudaGetSymbolAddress((void**)&p_encproj, g_enc_proj);
    cudaGetSymbolAddress((void**)&p_Mdec,    g_Mdec);
    cudaGetSymbolAddress((void**)&p_Wih,     g_Wih_p);
    cudaGetSymbolAddress((void**)&p_Whh,     g_Whh_p);
    cudaGetSymbolAddress((void**)&p_W1r,     g_W1r);
    cudaGetSymbolAddress((void**)&p_xall,    g_xall);

    // prep
    k_prep_enc<<<G4, H_>>>(W_ih_enc, W_hh_enc, b_ih_enc, b_hh_enc);
    k_prep_dec<<<NDEC, H_>>>(W_hh_dec, W2);
    k_prep_W1<<<W_, H_>>>(W1);
    k_xproj<<<(B_ * G4 + 255) / 256, 256>>>(dec_in, W_ih_dec, b_ih_dec, b_hh_dec);
    k_zero<<<(B_ * H_ + 255) / 256, 256>>>();

    // xall = x @ W_ih_enc^T + biases   (rows b*S+t, K=64)
    gemm_tf32<1><<<dim3(G4 / 64, (B_ * S_) / 64), 128>>>(x, IN_, p_Wih, IN_,
                                                         p_xall, G4, IN_, 0);

    // encoder: 128 sequential fused GEMM+LSTM steps (h double-buffered)
    for (int t = 0; t < S_; t++) {
        const float* hin = (t & 1) ? p_hB : p_hA;
        float*       hout = (t & 1) ? p_hA : p_hB;
        gemm_tf32<2><<<dim3(G4 / 64, B_ / 64), 128>>>(hin, H_, p_Whh, H_,
                                                      hout, H_, H_, t);
    }
    // h_last in g_hA, c_last in g_c

    // enc_proj = enc_outs @ W1^T   [S*B, W]
    gemm_tf32<0><<<dim3(W_ / 64, (S_ * B_) / 64), 128>>>(p_encouts, H_, p_W1r, H_,
                                                         p_encproj, W_, H_, 0);

    // decoder prime: hd0 = cell(h_last)
    gemm_tf32<3><<<dim3(NDEC / 64, B_ / 64), 128>>>(p_hA, H_, p_Mdec, H_,
                                                    p_hd0, H_, H_, 0);

    // decoder loop: GEMM produces next hidden (fused cell) + hw2 of current hidden
    for (int t = 0; t < S_; t++) {
        const float* Acur = (t & 1) ? p_hd1 : p_hd0;
        float*       Hnxt = (t & 1) ? p_hd0 : p_hd1;
        gemm_tf32<3><<<dim3(NDEC / 64, B_ / 64), 128>>>(Acur, H_, p_Mdec, H_,
                                                        Hnxt, H_, H_, t);
        attn_softmax<<<B_, 512>>>(t, vt, out);
    }

    (void)in_sizes; (void)n_in; (void)out_size;
}

// round 3
// speedup vs baseline: 2.3238x; 1.2706x over previous
#include <cuda_runtime.h>
#include <cstdint>
#include <cstddef>

#define B_   256
#define S_   128
#define IN_  64
#define H_   512
#define W_   512
#define G4   2048   // 4*H
#define NDEC 2560   // G4 + W
#define NTILE_DEC 80
#define BSTRIDE 516 // padded smem row stride (conflict-free)

// ---------------- device globals ----------------
__device__ float g_Wih_p[G4 * IN_];
__device__ float g_Whh_p[G4 * H_];
__device__ float g_bc_enc[G4];
__device__ float g_Mdec[NDEC * H_];                 // permuted W_hh_dec | W2 (tf32)
__device__ float g_Wihdec_p[G4 * IN_];
__device__ float g_bdec[G4];
__device__ float g_W1r[W_ * H_];
__device__ float g_xproj[B_ * G4];
__device__ float g_xall[(size_t)B_ * S_ * G4];
__device__ float g_hA[B_ * H_];
__device__ float g_hB[B_ * H_];
__device__ float g_c[B_ * H_];
__device__ float g_hd0[B_ * H_];
__device__ float g_hd1[B_ * H_];
__device__ float g_enc_outs[(size_t)S_ * B_ * H_];
__device__ float g_enc_proj[(size_t)S_ * B_ * W_];
__device__ float g_hw2all[(size_t)S_ * B_ * W_];    // [t][b][w]
__device__ volatile unsigned g_barE[S_];
__device__ volatile unsigned g_barD[S_ + 2];

// ---------------- helpers ----------------
__device__ __forceinline__ float sigf(float x) { return 1.0f / (1.0f + __expf(-x)); }
__device__ __forceinline__ float fast_tanh(float x) {
    float y; asm("tanh.approx.f32 %0, %1;" : "=f"(y) : "f"(x)); return y;
}
__device__ __forceinline__ uint32_t tf32r(float x) {
    uint32_t u; asm("cvt.rna.tf32.f32 %0, %1;" : "=r"(u) : "f"(x)); return u;
}
__device__ __forceinline__ void mma8(float* d, const uint32_t* a, const uint32_t* b) {
    asm volatile("mma.sync.aligned.m16n8k8.row.col.f32.tf32.tf32.f32 "
        "{%0,%1,%2,%3}, {%4,%5,%6,%7}, {%8,%9}, {%0,%1,%2,%3};"
        : "+f"(d[0]), "+f"(d[1]), "+f"(d[2]), "+f"(d[3])
        : "r"(a[0]), "r"(a[1]), "r"(a[2]), "r"(a[3]), "r"(b[0]), "r"(b[1]));
}
__device__ __forceinline__ float4 ldcg4(const float* p) {
    float4 v;
    asm volatile("ld.global.cg.v4.f32 {%0,%1,%2,%3}, [%4];"
        : "=f"(v.x), "=f"(v.y), "=f"(v.z), "=f"(v.w) : "l"(p));
    return v;
}
__device__ __forceinline__ void gridbar(volatile unsigned* slot, unsigned n) {
    __syncthreads();
    if (threadIdx.x == 0) {
        __threadfence();
        atomicAdd((unsigned*)slot, 1u);
        while (*slot < n) { asm volatile("nanosleep.u32 64;"); }
        __threadfence();
    }
    __syncthreads();
}

// ---------------- prep ----------------
__global__ void k_prep_enc(const float* __restrict__ Wih, const float* __restrict__ Whh,
                           const float* __restrict__ bih, const float* __restrict__ bhh) {
    int q = blockIdx.x, k = threadIdx.x;
    int j = q >> 2, g = q & 3;
    int r = g * H_ + j;
    g_Whh_p[q * H_ + k] = __uint_as_float(tf32r(Whh[r * H_ + k]));
    if (k < IN_) g_Wih_p[q * IN_ + k] = __uint_as_float(tf32r(Wih[r * IN_ + k]));
    if (k == 0)  g_bc_enc[q] = bih[r] + bhh[r];
}
__global__ void k_prep_dec(const float* __restrict__ Whh, const float* __restrict__ W2,
                           const float* __restrict__ Wih,
                           const float* __restrict__ bih, const float* __restrict__ bhh) {
    int q = blockIdx.x, k = threadIdx.x;
    float v;
    if (q < G4) {
        int j = q >> 2, g = q & 3;
        int r = g * H_ + j;
        v = Whh[r * H_ + k];
        if (k < IN_) g_Wihdec_p[q * IN_ + k] = __uint_as_float(tf32r(Wih[r * IN_ + k]));
        if (k == 0)  g_bdec[q] = bih[r] + bhh[r];
    } else {
        v = W2[(q - G4) * H_ + k];
    }
    g_Mdec[q * H_ + k] = __uint_as_float(tf32r(v));
}
__global__ void k_prep_W1(const float* __restrict__ W1) {
    int n = blockIdx.x, k = threadIdx.x;
    g_W1r[n * H_ + k] = __uint_as_float(tf32r(W1[n * H_ + k]));
}
__global__ void k_zero() {
    int idx = blockIdx.x * blockDim.x + threadIdx.x;
    if (idx < B_ * H_) { g_hA[idx] = 0.0f; g_c[idx] = 0.0f; }
    if (idx < S_)      g_barE[idx] = 0u;
    if (idx < S_ + 2)  g_barD[idx] = 0u;
}

// ---------------- generic tf32 GEMM (xall / xproj / enc_proj) ----------------
// C[M,N] = A[M,K] @ Bw[N,K]^T (+bias[n] if MODE==1)
template<int MODE>
__global__ __launch_bounds__(128)
void gemm_tf32(const float* __restrict__ A, int lda,
               const float* __restrict__ Bw, int ldb,
               float* __restrict__ C, int ldc, int K,
               const float* __restrict__ bias)
{
    __shared__ float As[64][36];
    __shared__ float Bs[64][36];
    int tid = threadIdx.x, lane = tid & 31, warp = tid >> 5;
    int wm = warp >> 1, wn = warp & 1;
    int gid = lane >> 2, tig = lane & 3;
    int m0 = blockIdx.y * 64, n0 = blockIdx.x * 64;

    float acc[2][4][4];
    #pragma unroll
    for (int a = 0; a < 2; a++) for (int b = 0; b < 4; b++) for (int c = 0; c < 4; c++)
        acc[a][b][c] = 0.0f;

    float4 ra[4], rb[4];
    int lrow[4], lc4[4];
    #pragma unroll
    for (int i = 0; i < 4; i++) { int idx = tid + i * 128; lrow[i] = idx >> 3; lc4[i] = (idx & 7) * 4; }

    #pragma unroll
    for (int i = 0; i < 4; i++) {
        ra[i] = *(const float4*)&A [(size_t)(m0 + lrow[i]) * lda + lc4[i]];
        rb[i] = *(const float4*)&Bw[(size_t)(n0 + lrow[i]) * ldb + lc4[i]];
    }
    #pragma unroll
    for (int i = 0; i < 4; i++) {
        float4 va;
        va.x = __uint_as_float(tf32r(ra[i].x)); va.y = __uint_as_float(tf32r(ra[i].y));
        va.z = __uint_as_float(tf32r(ra[i].z)); va.w = __uint_as_float(tf32r(ra[i].w));
        *(float4*)&As[lrow[i]][lc4[i]] = va;
        *(float4*)&Bs[lrow[i]][lc4[i]] = rb[i];
    }
    __syncthreads();

    int nIt = K >> 5;
    for (int it = 0; it < nIt; it++) {
        if (it + 1 < nIt) {
            int k0 = (it + 1) << 5;
            #pragma unroll
            for (int i = 0; i < 4; i++) {
                ra[i] = *(const float4*)&A [(size_t)(m0 + lrow[i]) * lda + k0 + lc4[i]];
                rb[i] = *(const float4*)&Bw[(size_t)(n0 + lrow[i]) * ldb + k0 + lc4[i]];
            }
        }
        #pragma unroll
        for (int k8 = 0; k8 < 4; k8++) {
            int kc = k8 * 8;
            uint32_t af[2][4], bf[4][2];
            #pragma unroll
            for (int mt = 0; mt < 2; mt++) {
                int r = wm * 32 + mt * 16 + gid;
                af[mt][0] = __float_as_uint(As[r    ][kc + tig]);
                af[mt][1] = __float_as_uint(As[r + 8][kc + tig]);
                af[mt][2] = __float_as_uint(As[r    ][kc + tig + 4]);
                af[mt][3] = __float_as_uint(As[r + 8][kc + tig + 4]);
            }
            #pragma unroll
            for (int nt = 0; nt < 4; nt++) {
                int n = wn * 32 + nt * 8 + gid;
                bf[nt][0] = __float_as_uint(Bs[n][kc + tig]);
                bf[nt][1] = __float_as_uint(Bs[n][kc + tig + 4]);
            }
            #pragma unroll
            for (int mt = 0; mt < 2; mt++)
                #pragma unroll
                for (int nt = 0; nt < 4; nt++) mma8(acc[mt][nt], af[mt], bf[nt]);
        }
        __syncthreads();
        if (it + 1 < nIt) {
            #pragma unroll
            for (int i = 0; i < 4; i++) {
                float4 va;
                va.x = __uint_as_float(tf32r(ra[i].x)); va.y = __uint_as_float(tf32r(ra[i].y));
                va.z = __uint_as_float(tf32r(ra[i].z)); va.w = __uint_as_float(tf32r(ra[i].w));
                *(float4*)&As[lrow[i]][lc4[i]] = va;
                *(float4*)&Bs[lrow[i]][lc4[i]] = rb[i];
            }
            __syncthreads();
        }
    }
    #pragma unroll
    for (int mt = 0; mt < 2; mt++) {
        #pragma unroll
        for (int nt = 0; nt < 4; nt++) {
            float c0 = acc[mt][nt][0], c1 = acc[mt][nt][1], c2 = acc[mt][nt][2], c3 = acc[mt][nt][3];
            int rr = m0 + wm * 32 + mt * 16 + gid;
            int cc = n0 + wn * 32 + nt * 8 + 2 * tig;
            if (MODE == 1) {
                float b0 = bias[cc], b1 = bias[cc + 1];
                c0 += b0; c1 += b1; c2 += b0; c3 += b1;
            }
            *(float2*)&C[(size_t)rr * ldc + cc]       = make_float2(c0, c1);
            *(float2*)&C[(size_t)(rr + 8) * ldc + cc] = make_float2(c2, c3);
        }
    }
}

// ---------------- persistent encoder: 128 steps, grid 128 CTAs ----------------
__global__ __launch_bounds__(128)
void enc_persist() {
    extern __shared__ float sm[];
    float* Bsm = sm;                          // [64][516]
    float* Asm = sm + 64 * BSTRIDE;           // [2][64][36]
    int tid = threadIdx.x, lane = tid & 31, warp = tid >> 5;
    int wm = warp >> 1, wn = warp & 1, gid = lane >> 2, tig = lane & 3;
    int bid = blockIdx.x;
    int m0 = (bid >> 5) * 64, n0 = (bid & 31) * 64;

    // preload B tile (resident whole kernel)
    for (int i = tid; i < 64 * 128; i += 128) {
        int r = i >> 7, c4 = (i & 127) * 4;
        float4 v = *(const float4*)&g_Whh_p[(size_t)(n0 + r) * H_ + c4];
        float* d = &Bsm[r * BSTRIDE + c4];
        d[0] = v.x; d[1] = v.y; d[2] = v.z; d[3] = v.w;
    }
    int lrow[4], lc4[4];
    #pragma unroll
    for (int i = 0; i < 4; i++) { int idx = tid + i * 128; lrow[i] = idx >> 3; lc4[i] = (idx & 7) * 4; }
    __syncthreads();

    for (int t = 0; t < S_; t++) {
        const float* A = (t & 1) ? g_hB : g_hA;
        float*      hout = (t & 1) ? g_hA : g_hB;

        float4 ra[4];
        #pragma unroll
        for (int i = 0; i < 4; i++) ra[i] = ldcg4(&A[(size_t)(m0 + lrow[i]) * H_ + lc4[i]]);
        #pragma unroll
        for (int i = 0; i < 4; i++) *(float4*)&Asm[lrow[i] * 36 + lc4[i]] = ra[i];
        __syncthreads();

        float acc[2][4][4];
        #pragma unroll
        for (int a = 0; a < 2; a++) for (int b = 0; b < 4; b++) for (int c = 0; c < 4; c++)
            acc[a][b][c] = 0.0f;

        for (int it = 0; it < 16; it++) {
            if (it < 15) {
                int k0 = (it + 1) * 32;
                #pragma unroll
                for (int i = 0; i < 4; i++)
                    ra[i] = ldcg4(&A[(size_t)(m0 + lrow[i]) * H_ + k0 + lc4[i]]);
            }
            const float* Ab = &Asm[(it & 1) * 64 * 36];
            int kb = it * 32;
            #pragma unroll
            for (int k8 = 0; k8 < 4; k8++) {
                int kc = k8 * 8;
                uint32_t af[2][4], bf[4][2];
                #pragma unroll
                for (int mt = 0; mt < 2; mt++) {
                    int r = wm * 32 + mt * 16 + gid;
                    af[mt][0] = __float_as_uint(Ab[r * 36 + kc + tig]);
                    af[mt][1] = __float_as_uint(Ab[(r + 8) * 36 + kc + tig]);
                    af[mt][2] = __float_as_uint(Ab[r * 36 + kc + tig + 4]);
                    af[mt][3] = __float_as_uint(Ab[(r + 8) * 36 + kc + tig + 4]);
                }
                #pragma unroll
                for (int nt = 0; nt < 4; nt++) {
                    int n = wn * 32 + nt * 8 + gid;
                    bf[nt][0] = __float_as_uint(Bsm[n * BSTRIDE + kb + kc + tig]);
                    bf[nt][1] = __float_as_uint(Bsm[n * BSTRIDE + kb + kc + tig + 4]);
                }
                #pragma unroll
                for (int mt = 0; mt < 2; mt++)
                    #pragma unroll
                    for (int nt = 0; nt < 4; nt++) mma8(acc[mt][nt], af[mt], bf[nt]);
            }
            if (it < 15) {
                float* Aw = &Asm[((it + 1) & 1) * 64 * 36];
                #pragma unroll
                for (int i = 0; i < 4; i++) *(float4*)&Aw[lrow[i] * 36 + lc4[i]] = ra[i];
            }
            __syncthreads();
        }

        // fused LSTM epilogue
        #pragma unroll
        for (int mt = 0; mt < 2; mt++) {
            #pragma unroll
            for (int nt = 0; nt < 4; nt++) {
                float c0 = acc[mt][nt][0], c1 = acc[mt][nt][1], c2 = acc[mt][nt][2], c3 = acc[mt][nt][3];
                float x0 = __shfl_xor_sync(0xFFFFFFFFu, c0, 1);
                float x1 = __shfl_xor_sync(0xFFFFFFFFu, c1, 1);
                float x2 = __shfl_xor_sync(0xFFFFFFFFu, c2, 1);
                float x3 = __shfl_xor_sync(0xFFFFFFFFu, c3, 1);
                int p = tig & 1;
                int rr = m0 + wm * 32 + mt * 16 + gid;
                int r  = rr + (p ? 8 : 0);
                int j  = ((n0 + wn * 32 + nt * 8) >> 2) + (tig >> 1);
                float gi = p ? x2 : c0;
                float gf = p ? x3 : c1;
                float gg = p ? c2 : x0;
                float go = p ? c3 : x1;
                float4 xa = *(const float4*)&g_xall[((size_t)r * S_ + t) * G4 + 4 * j];
                float i_ = sigf(gi + xa.x);
                float f_ = sigf(gf + xa.y);
                float g_ = tanhf(gg + xa.z);
                float o_ = sigf(go + xa.w);
                float cn = f_ * g_c[r * H_ + j] + i_ * g_;
                g_c[r * H_ + j] = cn;
                float h = o_ * tanhf(cn);
                float hr = __uint_as_float(tf32r(h));
                hout[(size_t)r * H_ + j] = hr;
                g_enc_outs[((size_t)t * B_ + r) * H_ + j] = hr;
            }
        }
        gridbar(&g_barE[t], 128);
    }
}

// ---------------- persistent decoder hidden chain: 129 steps, grid 128 CTAs ----------------
// tile 64(M) x 80(N); gates cols [0,2048) -> hd; cols [2048,2560) -> hw2_all
__global__ __launch_bounds__(128)
void dec_chain() {
    extern __shared__ float sm[];
    float* Bsm = sm;                          // [80][516]
    float* Asm = sm + NTILE_DEC * BSTRIDE;    // [2][64][36]
    int tid = threadIdx.x, lane = tid & 31, warp = tid >> 5;
    int wm = warp >> 1, wn = warp & 1, gid = lane >> 2, tig = lane & 3;
    int bid = blockIdx.x;
    int m0 = (bid & 3) * 64, n0 = (bid >> 2) * NTILE_DEC;

    for (int i = tid; i < NTILE_DEC * 128; i += 128) {
        int r = i >> 7, c4 = (i & 127) * 4;
        float4 v = *(const float4*)&g_Mdec[(size_t)(n0 + r) * H_ + c4];
        float* d = &Bsm[r * BSTRIDE + c4];
        d[0] = v.x; d[1] = v.y; d[2] = v.z; d[3] = v.w;
    }
    int lrow[4], lc4[4];
    #pragma unroll
    for (int i = 0; i < 4; i++) { int idx = tid + i * 128; lrow[i] = idx >> 3; lc4[i] = (idx & 7) * 4; }
    __syncthreads();

    for (int st = 0; st <= S_; st++) {
        const float* A = (st == 0) ? g_hA : ((st & 1) ? g_hd0 : g_hd1);
        float*      hout = (st & 1) ? g_hd1 : g_hd0;

        float4 ra[4];
        #pragma unroll
        for (int i = 0; i < 4; i++) ra[i] = ldcg4(&A[(size_t)(m0 + lrow[i]) * H_ + lc4[i]]);
        #pragma unroll
        for (int i = 0; i < 4; i++) *(float4*)&Asm[lrow[i] * 36 + lc4[i]] = ra[i];
        __syncthreads();

        float acc[2][5][4];
        #pragma unroll
        for (int a = 0; a < 2; a++) for (int b = 0; b < 5; b++) for (int c = 0; c < 4; c++)
            acc[a][b][c] = 0.0f;

        for (int it = 0; it < 16; it++) {
            if (it < 15) {
                int k0 = (it + 1) * 32;
                #pragma unroll
                for (int i = 0; i < 4; i++)
                    ra[i] = ldcg4(&A[(size_t)(m0 + lrow[i]) * H_ + k0 + lc4[i]]);
            }
            const float* Ab = &Asm[(it & 1) * 64 * 36];
            int kb = it * 32;
            #pragma unroll
            for (int k8 = 0; k8 < 4; k8++) {
                int kc = k8 * 8;
                uint32_t af[2][4], bf[5][2];
                #pragma unroll
                for (int mt = 0; mt < 2; mt++) {
                    int r = wm * 32 + mt * 16 + gid;
                    af[mt][0] = __float_as_uint(Ab[r * 36 + kc + tig]);
                    af[mt][1] = __float_as_uint(Ab[(r + 8) * 36 + kc + tig]);
                    af[mt][2] = __float_as_uint(Ab[r * 36 + kc + tig + 4]);
                    af[mt][3] = __float_as_uint(Ab[(r + 8) * 36 + kc + tig + 4]);
                }
                #pragma unroll
                for (int nt = 0; nt < 5; nt++) {
                    int n = wn * 40 + nt * 8 + gid;
                    bf[nt][0] = __float_as_uint(Bsm[n * BSTRIDE + kb + kc + tig]);
                    bf[nt][1] = __float_as_uint(Bsm[n * BSTRIDE + kb + kc + tig + 4]);
                }
                #pragma unroll
                for (int mt = 0; mt < 2; mt++)
                    #pragma unroll
                    for (int nt = 0; nt < 5; nt++) mma8(acc[mt][nt], af[mt], bf[nt]);
            }
            if (it < 15) {
                float* Aw = &Asm[((it + 1) & 1) * 64 * 36];
                #pragma unroll
                for (int i = 0; i < 4; i++) *(float4*)&Aw[lrow[i] * 36 + lc4[i]] = ra[i];
            }
            __syncthreads();
        }

        bool do_gates = (st < S_);
        bool do_hw2   = (st > 0);
        #pragma unroll
        for (int mt = 0; mt < 2; mt++) {
            #pragma unroll
            for (int nt = 0; nt < 5; nt++) {
                int fb = n0 + wn * 40 + nt * 8;   // frag base col (warp-uniform)
                float c0 = acc[mt][nt][0], c1 = acc[mt][nt][1], c2 = acc[mt][nt][2], c3 = acc[mt][nt][3];
                int rr = m0 + wm * 32 + mt * 16 + gid;
                if (fb < G4) {
                    if (!do_gates) continue;
                    float x0 = __shfl_xor_sync(0xFFFFFFFFu, c0, 1);
                    float x1 = __shfl_xor_sync(0xFFFFFFFFu, c1, 1);
                    float x2 = __shfl_xor_sync(0xFFFFFFFFu, c2, 1);
                    float x3 = __shfl_xor_sync(0xFFFFFFFFu, c3, 1);
                    int p = tig & 1;
                    int r = rr + (p ? 8 : 0);
                    int j = (fb >> 2) + (tig >> 1);
                    float gi = p ? x2 : c0;
                    float gf = p ? x3 : c1;
                    float gg = p ? c2 : x0;
                    float go = p ? c3 : x1;
                    float4 xa = *(const float4*)&g_xproj[(size_t)r * G4 + 4 * j];
                    float i_ = sigf(gi + xa.x);
                    float f_ = sigf(gf + xa.y);
                    float g_ = tanhf(gg + xa.z);
                    float o_ = sigf(go + xa.w);
                    float cn = f_ * g_c[r * H_ + j] + i_ * g_;   // c fixed (read-only)
                    float h = o_ * tanhf(cn);
                    hout[(size_t)r * H_ + j] = __uint_as_float(tf32r(h));
                } else {
                    if (!do_hw2) continue;
                    int cc = fb + 2 * tig - G4;
                    size_t base = ((size_t)(st - 1) * B_ + rr) * W_;
                    *(float2*)&g_hw2all[base + cc]            = make_float2(c0, c1);
                    *(float2*)&g_hw2all[base + (size_t)8 * W_ + cc] = make_float2(c2, c3);
                }
            }
        }
        gridbar(&g_barD[st], 128);
    }
}

// ---------------- mega attention: grid (256 b, 8 t-tiles), 256 thr ----------------
__global__ __launch_bounds__(256)
void attn_mega(const float* __restrict__ vt, float* __restrict__ out) {
    __shared__ float hw2s[16 * 512];
    __shared__ float sc[16 * 128];
    int b = blockIdx.x, t0 = blockIdx.y * 16;
    int tid = threadIdx.x, lane = tid & 31, w = tid >> 5;

    for (int i = tid * 4; i < 16 * 512; i += 256 * 4) {
        int t = i >> 9, c = i & 511;
        *(float4*)&hw2s[i] = *(const float4*)&g_hw2all[((size_t)(t0 + t) * B_ + b) * W_ + c];
    }
    float4 vv[4];
    #pragma unroll
    for (int j = 0; j < 4; j++) vv[j] = *(const float4*)&vt[j * 128 + lane * 4];
    __syncthreads();

    float4 er[4], ern[4];
    {
        const float* ep = &g_enc_proj[((size_t)w * B_ + b) * W_];
        #pragma unroll
        for (int j = 0; j < 4; j++) er[j] = *(const float4*)&ep[j * 128 + lane * 4];
    }
    for (int si = 0; si < 16; si++) {
        int s = si * 8 + w;
        if (si < 15) {
            const float* ep = &g_enc_proj[((size_t)(s + 8) * B_ + b) * W_];
            #pragma unroll
            for (int j = 0; j < 4; j++) ern[j] = *(const float4*)&ep[j * 128 + lane * 4];
        }
        #pragma unroll 4
        for (int tl = 0; tl < 16; tl++) {
            float a = 0.0f;
            #pragma unroll
            for (int j = 0; j < 4; j++) {
                float4 hv = *(const float4*)&hw2s[tl * 512 + j * 128 + lane * 4];
                a += fast_tanh(er[j].x + hv.x) * vv[j].x;
                a += fast_tanh(er[j].y + hv.y) * vv[j].y;
                a += fast_tanh(er[j].z + hv.z) * vv[j].z;
                a += fast_tanh(er[j].w + hv.w) * vv[j].w;
            }
            #pragma unroll
            for (int off = 16; off; off >>= 1) a += __shfl_xor_sync(0xFFFFFFFFu, a, off);
            if (lane == 0) sc[tl * 128 + s] = a;
        }
        #pragma unroll
        for (int j = 0; j < 4; j++) er[j] = ern[j];
    }
    __syncthreads();

    for (int tl = w; tl < 16; tl += 8) {
        float4 v = *(const float4*)&sc[tl * 128 + lane * 4];
        float m = fmaxf(fmaxf(v.x, v.y), fmaxf(v.z, v.w));
        #pragma unroll
        for (int off = 16; off; off >>= 1) m = fmaxf(m, __shfl_xor_sync(0xFFFFFFFFu, m, off));
        float e = __expf(v.x - m) + __expf(v.y - m) + __expf(v.z - m) + __expf(v.w - m);
        #pragma unroll
        for (int off = 16; off; off >>= 1) e += __shfl_xor_sync(0xFFFFFFFFu, e, off);
        float L = m + logf(e);
        float4 o = make_float4(v.x - L, v.y - L, v.z - L, v.w - L);
        *(float4*)&out[((size_t)b * S_ + (t0 + tl)) * S_ + lane * 4] = o;
    }
}

// ---------------- launch ----------------
extern "C" void kernel_launch(void* const* d_in, const int* in_sizes, int n_in,
                              void* d_out, int out_size) {
    const float* x        = (const float*)d_in[0];
    const float* dec_in   = (const float*)d_in[1];
    const float* W_ih_enc = (const float*)d_in[2];
    const float* W_hh_enc = (const float*)d_in[3];
    const float* b_ih_enc = (const float*)d_in[4];
    const float* b_hh_enc = (const float*)d_in[5];
    const float* W_ih_dec = (const float*)d_in[6];
    const float* W_hh_dec = (const float*)d_in[7];
    const float* b_ih_dec = (const float*)d_in[8];
    const float* b_hh_dec = (const float*)d_in[9];
    const float* W1       = (const float*)d_in[10];
    const float* W2       = (const float*)d_in[11];
    const float* vt       = (const float*)d_in[12];
    float* out = (float*)d_out;

    float *p_encouts, *p_encproj, *p_Wih, *p_W1r, *p_xall, *p_xproj, *p_bce,
          *p_Wihdec, *p_bdec;
    cudaGetSymbolAddress((void**)&p_encouts, g_enc_outs);
    cudaGetSymbolAddress((void**)&p_encproj, g_enc_proj);
    cudaGetSymbolAddress((void**)&p_Wih,     g_Wih_p);
    cudaGetSymbolAddress((void**)&p_W1r,     g_W1r);
    cudaGetSymbolAddress((void**)&p_xall,    g_xall);
    cudaGetSymbolAddress((void**)&p_xproj,   g_xproj);
    cudaGetSymbolAddress((void**)&p_bce,     g_bc_enc);
    cudaGetSymbolAddress((void**)&p_Wihdec,  g_Wihdec_p);
    cudaGetSymbolAddress((void**)&p_bdec,    g_bdec);

    const int ENC_SMEM = (64 * BSTRIDE + 2 * 64 * 36) * 4;          // 150,528
    const int DEC_SMEM = (NTILE_DEC * BSTRIDE + 2 * 64 * 36) * 4;   // 183,552
    cudaFuncSetAttribute(enc_persist, cudaFuncAttributeMaxDynamicSharedMemorySize, ENC_SMEM);
    cudaFuncSetAttribute(dec_chain,   cudaFuncAttributeMaxDynamicSharedMemorySize, DEC_SMEM);

    // prep
    k_prep_enc<<<G4, H_>>>(W_ih_enc, W_hh_enc, b_ih_enc, b_hh_enc);
    k_prep_dec<<<NDEC, H_>>>(W_hh_dec, W2, W_ih_dec, b_ih_dec, b_hh_dec);
    k_prep_W1<<<W_, H_>>>(W1);
    k_zero<<<(B_ * H_ + 255) / 256, 256>>>();

    // xall = x @ W_ih_enc^T + bias  (rows b*S+t)
    gemm_tf32<1><<<dim3(G4 / 64, (B_ * S_) / 64), 128>>>(x, IN_, p_Wih, IN_,
                                                         p_xall, G4, IN_, p_bce);
    // xproj = dec_in @ W_ih_dec^T + bias
    gemm_tf32<1><<<dim3(G4 / 64, B_ / 64), 128>>>(dec_in, IN_, p_Wihdec, IN_,
                                                  p_xproj, G4, IN_, p_bdec);

    // persistent encoder (h_last -> g_hA, c_last -> g_c)
    enc_persist<<<128, 128, ENC_SMEM>>>();

    // enc_proj = enc_outs @ W1^T
    gemm_tf32<0><<<dim3(W_ / 64, (S_ * B_) / 64), 128>>>(p_encouts, H_, p_W1r, H_,
                                                         p_encproj, W_, H_, nullptr);

    // persistent decoder hidden chain -> g_hw2all
    dec_chain<<<128, 128, DEC_SMEM>>>();

    // mega attention + log_softmax
    attn_mega<<<dim3(B_, 8), 256>>>(vt, out);

    (void)in_sizes; (void)n_in; (void)out_size;
}

// round 4
// speedup vs baseline: 2.3264x; 1.0011x over previous
#include <cuda_runtime.h>
#include <cstdint>
#include <cstddef>

#define B_   256
#define S_   128
#define IN_  64
#define H_   512
#define W_   512
#define G4   2048   // 4*H
#define NDEC 2560   // G4 + W
#define NTILE_DEC 80
#define BSTRIDE 516 // padded smem row stride (conflict-free)

// ---------------- device globals ----------------
__device__ float g_Wih_p[G4 * IN_];
__device__ float g_Whh_p[G4 * H_];
__device__ float g_bc_enc[G4];
__device__ float g_Mdec[NDEC * H_];                 // permuted W_hh_dec | W2 (tf32)
__device__ float g_Wihdec_p[G4 * IN_];
__device__ float g_bdec[G4];
__device__ float g_W1r[W_ * H_];
__device__ float g_xproj[B_ * G4];
__device__ float g_xall[(size_t)B_ * S_ * G4];
__device__ float g_hA[B_ * H_];
__device__ float g_hB[B_ * H_];
__device__ float g_c[B_ * H_];
__device__ float g_hd0[B_ * H_];
__device__ float g_hd1[B_ * H_];
__device__ float g_enc_outs[(size_t)S_ * B_ * H_];
__device__ float g_enc_proj[(size_t)S_ * B_ * W_];
__device__ float g_hw2all[(size_t)S_ * B_ * W_];    // [t][b][w]
__device__ volatile unsigned g_barE[S_];
__device__ volatile unsigned g_barD[S_ + 2];

// ---------------- helpers ----------------
__device__ __forceinline__ float sigf(float x) { return 1.0f / (1.0f + __expf(-x)); }
__device__ __forceinline__ float fast_tanh(float x) {
    float y; asm("tanh.approx.f32 %0, %1;" : "=f"(y) : "f"(x)); return y;
}
__device__ __forceinline__ uint32_t tf32r(float x) {
    uint32_t u; asm("cvt.rna.tf32.f32 %0, %1;" : "=r"(u) : "f"(x)); return u;
}
__device__ __forceinline__ void mma8(float* d, const uint32_t* a, const uint32_t* b) {
    asm volatile("mma.sync.aligned.m16n8k8.row.col.f32.tf32.tf32.f32 "
        "{%0,%1,%2,%3}, {%4,%5,%6,%7}, {%8,%9}, {%0,%1,%2,%3};"
        : "+f"(d[0]), "+f"(d[1]), "+f"(d[2]), "+f"(d[3])
        : "r"(a[0]), "r"(a[1]), "r"(a[2]), "r"(a[3]), "r"(b[0]), "r"(b[1]));
}
__device__ __forceinline__ float4 ldcg4(const float* p) {
    float4 v;
    asm volatile("ld.global.cg.v4.f32 {%0,%1,%2,%3}, [%4];"
        : "=f"(v.x), "=f"(v.y), "=f"(v.z), "=f"(v.w) : "l"(p));
    return v;
}
__device__ __forceinline__ void gridbar(volatile unsigned* slot, unsigned n) {
    __syncthreads();
    if (threadIdx.x == 0) {
        __threadfence();
        atomicAdd((unsigned*)slot, 1u);
        while (*slot < n) { asm volatile("nanosleep.u32 64;"); }
        __threadfence();
    }
    __syncthreads();
}

// ---------------- prep ----------------
__global__ void k_prep_enc(const float* __restrict__ Wih, const float* __restrict__ Whh,
                           const float* __restrict__ bih, const float* __restrict__ bhh) {
    int q = blockIdx.x, k = threadIdx.x;
    int j = q >> 2, g = q & 3;
    int r = g * H_ + j;
    g_Whh_p[q * H_ + k] = __uint_as_float(tf32r(Whh[r * H_ + k]));
    if (k < IN_) g_Wih_p[q * IN_ + k] = __uint_as_float(tf32r(Wih[r * IN_ + k]));
    if (k == 0)  g_bc_enc[q] = bih[r] + bhh[r];
}
__global__ void k_prep_dec(const float* __restrict__ Whh, const float* __restrict__ W2,
                           const float* __restrict__ Wih,
                           const float* __restrict__ bih, const float* __restrict__ bhh) {
    int q = blockIdx.x, k = threadIdx.x;
    float v;
    if (q < G4) {
        int j = q >> 2, g = q & 3;
        int r = g * H_ + j;
        v = Whh[r * H_ + k];
        if (k < IN_) g_Wihdec_p[q * IN_ + k] = __uint_as_float(tf32r(Wih[r * IN_ + k]));
        if (k == 0)  g_bdec[q] = bih[r] + bhh[r];
    } else {
        v = W2[(q - G4) * H_ + k];
    }
    g_Mdec[q * H_ + k] = __uint_as_float(tf32r(v));
}
__global__ void k_prep_W1(const float* __restrict__ W1) {
    int n = blockIdx.x, k = threadIdx.x;
    g_W1r[n * H_ + k] = __uint_as_float(tf32r(W1[n * H_ + k]));
}
__global__ void k_zero() {
    int idx = blockIdx.x * blockDim.x + threadIdx.x;
    if (idx < B_ * H_) { g_hA[idx] = 0.0f; g_c[idx] = 0.0f; }
    if (idx < S_)      g_barE[idx] = 0u;
    if (idx < S_ + 2)  g_barD[idx] = 0u;
}

// ---------------- generic tf32 GEMM (xall / xproj / enc_proj) ----------------
// C[M,N] = A[M,K] @ Bw[N,K]^T (+bias[n] if MODE==1)
template<int MODE>
__global__ __launch_bounds__(128)
void gemm_tf32(const float* __restrict__ A, int lda,
               const float* __restrict__ Bw, int ldb,
               float* __restrict__ C, int ldc, int K,
               const float* __restrict__ bias)
{
    __shared__ float As[64][36];
    __shared__ float Bs[64][36];
    int tid = threadIdx.x, lane = tid & 31, warp = tid >> 5;
    int wm = warp >> 1, wn = warp & 1;
    int gid = lane >> 2, tig = lane & 3;
    int m0 = blockIdx.y * 64, n0 = blockIdx.x * 64;

    float acc[2][4][4];
    #pragma unroll
    for (int a = 0; a < 2; a++) for (int b = 0; b < 4; b++) for (int c = 0; c < 4; c++)
        acc[a][b][c] = 0.0f;

    float4 ra[4], rb[4];
    int lrow[4], lc4[4];
    #pragma unroll
    for (int i = 0; i < 4; i++) { int idx = tid + i * 128; lrow[i] = idx >> 3; lc4[i] = (idx & 7) * 4; }

    #pragma unroll
    for (int i = 0; i < 4; i++) {
        ra[i] = *(const float4*)&A [(size_t)(m0 + lrow[i]) * lda + lc4[i]];
        rb[i] = *(const float4*)&Bw[(size_t)(n0 + lrow[i]) * ldb + lc4[i]];
    }
    #pragma unroll
    for (int i = 0; i < 4; i++) {
        float4 va;
        va.x = __uint_as_float(tf32r(ra[i].x)); va.y = __uint_as_float(tf32r(ra[i].y));
        va.z = __uint_as_float(tf32r(ra[i].z)); va.w = __uint_as_float(tf32r(ra[i].w));
        *(float4*)&As[lrow[i]][lc4[i]] = va;
        *(float4*)&Bs[lrow[i]][lc4[i]] = rb[i];
    }
    __syncthreads();

    int nIt = K >> 5;
    for (int it = 0; it < nIt; it++) {
        if (it + 1 < nIt) {
            int k0 = (it + 1) << 5;
            #pragma unroll
            for (int i = 0; i < 4; i++) {
                ra[i] = *(const float4*)&A [(size_t)(m0 + lrow[i]) * lda + k0 + lc4[i]];
                rb[i] = *(const float4*)&Bw[(size_t)(n0 + lrow[i]) * ldb + k0 + lc4[i]];
            }
        }
        #pragma unroll
        for (int k8 = 0; k8 < 4; k8++) {
            int kc = k8 * 8;
            uint32_t af[2][4], bf[4][2];
            #pragma unroll
            for (int mt = 0; mt < 2; mt++) {
                int r = wm * 32 + mt * 16 + gid;
                af[mt][0] = __float_as_uint(As[r    ][kc + tig]);
                af[mt][1] = __float_as_uint(As[r + 8][kc + tig]);
                af[mt][2] = __float_as_uint(As[r    ][kc + tig + 4]);
                af[mt][3] = __float_as_uint(As[r + 8][kc + tig + 4]);
            }
            #pragma unroll
            for (int nt = 0; nt < 4; nt++) {
                int n = wn * 32 + nt * 8 + gid;
                bf[nt][0] = __float_as_uint(Bs[n][kc + tig]);
                bf[nt][1] = __float_as_uint(Bs[n][kc + tig + 4]);
            }
            #pragma unroll
            for (int mt = 0; mt < 2; mt++)
                #pragma unroll
                for (int nt = 0; nt < 4; nt++) mma8(acc[mt][nt], af[mt], bf[nt]);
        }
        __syncthreads();
        if (it + 1 < nIt) {
            #pragma unroll
            for (int i = 0; i < 4; i++) {
                float4 va;
                va.x = __uint_as_float(tf32r(ra[i].x)); va.y = __uint_as_float(tf32r(ra[i].y));
                va.z = __uint_as_float(tf32r(ra[i].z)); va.w = __uint_as_float(tf32r(ra[i].w));
                *(float4*)&As[lrow[i]][lc4[i]] = va;
                *(float4*)&Bs[lrow[i]][lc4[i]] = rb[i];
            }
            __syncthreads();
        }
    }
    #pragma unroll
    for (int mt = 0; mt < 2; mt++) {
        #pragma unroll
        for (int nt = 0; nt < 4; nt++) {
            float c0 = acc[mt][nt][0], c1 = acc[mt][nt][1], c2 = acc[mt][nt][2], c3 = acc[mt][nt][3];
            int rr = m0 + wm * 32 + mt * 16 + gid;
            int cc = n0 + wn * 32 + nt * 8 + 2 * tig;
            if (MODE == 1) {
                float b0 = bias[cc], b1 = bias[cc + 1];
                c0 += b0; c1 += b1; c2 += b0; c3 += b1;
            }
            *(float2*)&C[(size_t)rr * ldc + cc]       = make_float2(c0, c1);
            *(float2*)&C[(size_t)(rr + 8) * ldc + cc] = make_float2(c2, c3);
        }
    }
}

// ---------------- persistent encoder: 128 steps, grid 128 CTAs ----------------
__global__ __launch_bounds__(128)
void enc_persist() {
    extern __shared__ float sm[];
    float* Bsm = sm;                          // [64][516]
    float* Asm = sm + 64 * BSTRIDE;           // [2][64][36]
    int tid = threadIdx.x, lane = tid & 31, warp = tid >> 5;
    int wm = warp >> 1, wn = warp & 1, gid = lane >> 2, tig = lane & 3;
    int bid = blockIdx.x;
    int m0 = (bid >> 5) * 64, n0 = (bid & 31) * 64;

    // preload B tile (resident whole kernel)
    for (int i = tid; i < 64 * 128; i += 128) {
        int r = i >> 7, c4 = (i & 127) * 4;
        float4 v = *(const float4*)&g_Whh_p[(size_t)(n0 + r) * H_ + c4];
        float* d = &Bsm[r * BSTRIDE + c4];
        d[0] = v.x; d[1] = v.y; d[2] = v.z; d[3] = v.w;
    }
    int lrow[4], lc4[4];
    #pragma unroll
    for (int i = 0; i < 4; i++) { int idx = tid + i * 128; lrow[i] = idx >> 3; lc4[i] = (idx & 7) * 4; }
    __syncthreads();

    for (int t = 0; t < S_; t++) {
        const float* A = (t & 1) ? g_hB : g_hA;
        float*      hout = (t & 1) ? g_hA : g_hB;

        float4 ra[4];
        #pragma unroll
        for (int i = 0; i < 4; i++) ra[i] = ldcg4(&A[(size_t)(m0 + lrow[i]) * H_ + lc4[i]]);
        #pragma unroll
        for (int i = 0; i < 4; i++) *(float4*)&Asm[lrow[i] * 36 + lc4[i]] = ra[i];
        __syncthreads();

        float acc[2][4][4];
        #pragma unroll
        for (int a = 0; a < 2; a++) for (int b = 0; b < 4; b++) for (int c = 0; c < 4; c++)
            acc[a][b][c] = 0.0f;

        for (int it = 0; it < 16; it++) {
            if (it < 15) {
                int k0 = (it + 1) * 32;
                #pragma unroll
                for (int i = 0; i < 4; i++)
                    ra[i] = ldcg4(&A[(size_t)(m0 + lrow[i]) * H_ + k0 + lc4[i]]);
            }
            const float* Ab = &Asm[(it & 1) * 64 * 36];
            int kb = it * 32;
            #pragma unroll
            for (int k8 = 0; k8 < 4; k8++) {
                int kc = k8 * 8;
                uint32_t af[2][4], bf[4][2];
                #pragma unroll
                for (int mt = 0; mt < 2; mt++) {
                    int r = wm * 32 + mt * 16 + gid;
                    af[mt][0] = __float_as_uint(Ab[r * 36 + kc + tig]);
                    af[mt][1] = __float_as_uint(Ab[(r + 8) * 36 + kc + tig]);
                    af[mt][2] = __float_as_uint(Ab[r * 36 + kc + tig + 4]);
                    af[mt][3] = __float_as_uint(Ab[(r + 8) * 36 + kc + tig + 4]);
                }
                #pragma unroll
                for (int nt = 0; nt < 4; nt++) {
                    int n = wn * 32 + nt * 8 + gid;
                    bf[nt][0] = __float_as_uint(Bsm[n * BSTRIDE + kb + kc + tig]);
                    bf[nt][1] = __float_as_uint(Bsm[n * BSTRIDE + kb + kc + tig + 4]);
                }
                #pragma unroll
                for (int mt = 0; mt < 2; mt++)
                    #pragma unroll
                    for (int nt = 0; nt < 4; nt++) mma8(acc[mt][nt], af[mt], bf[nt]);
            }
            if (it < 15) {
                float* Aw = &Asm[((it + 1) & 1) * 64 * 36];
                #pragma unroll
                for (int i = 0; i < 4; i++) *(float4*)&Aw[lrow[i] * 36 + lc4[i]] = ra[i];
            }
            __syncthreads();
        }

        // fused LSTM epilogue
        #pragma unroll
        for (int mt = 0; mt < 2; mt++) {
            #pragma unroll
            for (int nt = 0; nt < 4; nt++) {
                float c0 = acc[mt][nt][0], c1 = acc[mt][nt][1], c2 = acc[mt][nt][2], c3 = acc[mt][nt][3];
                float x0 = __shfl_xor_sync(0xFFFFFFFFu, c0, 1);
                float x1 = __shfl_xor_sync(0xFFFFFFFFu, c1, 1);
                float x2 = __shfl_xor_sync(0xFFFFFFFFu, c2, 1);
                float x3 = __shfl_xor_sync(0xFFFFFFFFu, c3, 1);
                int p = tig & 1;
                int rr = m0 + wm * 32 + mt * 16 + gid;
                int r  = rr + (p ? 8 : 0);
                int j  = ((n0 + wn * 32 + nt * 8) >> 2) + (tig >> 1);
                float gi = p ? x2 : c0;
                float gf = p ? x3 : c1;
                float gg = p ? c2 : x0;
                float go = p ? c3 : x1;
                float4 xa = *(const float4*)&g_xall[((size_t)r * S_ + t) * G4 + 4 * j];
                float i_ = sigf(gi + xa.x);
                float f_ = sigf(gf + xa.y);
                float g_ = tanhf(gg + xa.z);
                float o_ = sigf(go + xa.w);
                float cn = f_ * g_c[r * H_ + j] + i_ * g_;
                g_c[r * H_ + j] = cn;
                float h = o_ * tanhf(cn);
                float hr = __uint_as_float(tf32r(h));
                hout[(size_t)r * H_ + j] = hr;
                g_enc_outs[((size_t)t * B_ + r) * H_ + j] = hr;
            }
        }
        gridbar(&g_barE[t], 128);
    }
}

// ---------------- persistent decoder hidden chain: 129 steps, grid 128 CTAs ----------------
// tile 64(M) x 80(N); gates cols [0,2048) -> hd; cols [2048,2560) -> hw2_all
__global__ __launch_bounds__(128)
void dec_chain() {
    extern __shared__ float sm[];
    float* Bsm = sm;                          // [80][516]
    float* Asm = sm + NTILE_DEC * BSTRIDE;    // [2][64][36]
    int tid = threadIdx.x, lane = tid & 31, warp = tid >> 5;
    int wm = warp >> 1, wn = warp & 1, gid = lane >> 2, tig = lane & 3;
    int bid = blockIdx.x;
    int m0 = (bid & 3) * 64, n0 = (bid >> 2) * NTILE_DEC;

    for (int i = tid; i < NTILE_DEC * 128; i += 128) {
        int r = i >> 7, c4 = (i & 127) * 4;
        float4 v = *(const float4*)&g_Mdec[(size_t)(n0 + r) * H_ + c4];
        float* d = &Bsm[r * BSTRIDE + c4];
        d[0] = v.x; d[1] = v.y; d[2] = v.z; d[3] = v.w;
    }
    int lrow[4], lc4[4];
    #pragma unroll
    for (int i = 0; i < 4; i++) { int idx = tid + i * 128; lrow[i] = idx >> 3; lc4[i] = (idx & 7) * 4; }
    __syncthreads();

    for (int st = 0; st <= S_; st++) {
        const float* A = (st == 0) ? g_hA : ((st & 1) ? g_hd0 : g_hd1);
        float*      hout = (st & 1) ? g_hd1 : g_hd0;

        float4 ra[4];
        #pragma unroll
        for (int i = 0; i < 4; i++) ra[i] = ldcg4(&A[(size_t)(m0 + lrow[i]) * H_ + lc4[i]]);
        #pragma unroll
        for (int i = 0; i < 4; i++) *(float4*)&Asm[lrow[i] * 36 + lc4[i]] = ra[i];
        __syncthreads();

        float acc[2][5][4];
        #pragma unroll
        for (int a = 0; a < 2; a++) for (int b = 0; b < 5; b++) for (int c = 0; c < 4; c++)
            acc[a][b][c] = 0.0f;

        for (int it = 0; it < 16; it++) {
            if (it < 15) {
                int k0 = (it + 1) * 32;
                #pragma unroll
                for (int i = 0; i < 4; i++)
                    ra[i] = ldcg4(&A[(size_t)(m0 + lrow[i]) * H_ + k0 + lc4[i]]);
            }
            const float* Ab = &Asm[(it & 1) * 64 * 36];
            int kb = it * 32;
            #pragma unroll
            for (int k8 = 0; k8 < 4; k8++) {
                int kc = k8 * 8;
                uint32_t af[2][4], bf[5][2];
                #pragma unroll
                for (int mt = 0; mt < 2; mt++) {
                    int r = wm * 32 + mt * 16 + gid;
                    af[mt][0] = __float_as_uint(Ab[r * 36 + kc + tig]);
                    af[mt][1] = __float_as_uint(Ab[(r + 8) * 36 + kc + tig]);
                    af[mt][2] = __float_as_uint(Ab[r * 36 + kc + tig + 4]);
                    af[mt][3] = __float_as_uint(Ab[(r + 8) * 36 + kc + tig + 4]);
                }
                #pragma unroll
                for (int nt = 0; nt < 5; nt++) {
                    int n = wn * 40 + nt * 8 + gid;
                    bf[nt][0] = __float_as_uint(Bsm[n * BSTRIDE + kb + kc + tig]);
                    bf[nt][1] = __float_as_uint(Bsm[n * BSTRIDE + kb + kc + tig + 4]);
                }
                #pragma unroll
                for (int mt = 0; mt < 2; mt++)
                    #pragma unroll
                    for (int nt = 0; nt < 5; nt++) mma8(acc[mt][nt], af[mt], bf[nt]);
            }
            if (it < 15) {
                float* Aw = &Asm[((it + 1) & 1) * 64 * 36];
                #pragma unroll
                for (int i = 0; i < 4; i++) *(float4*)&Aw[lrow[i] * 36 + lc4[i]] = ra[i];
            }
            __syncthreads();
        }

        bool do_gates = (st < S_);
        bool do_hw2   = (st > 0);
        #pragma unroll
        for (int mt = 0; mt < 2; mt++) {
            #pragma unroll
            for (int nt = 0; nt < 5; nt++) {
                int fb = n0 + wn * 40 + nt * 8;   // frag base col (warp-uniform)
                float c0 = acc[mt][nt][0], c1 = acc[mt][nt][1], c2 = acc[mt][nt][2], c3 = acc[mt][nt][3];
                int rr = m0 + wm * 32 + mt * 16 + gid;
                if (fb < G4) {
                    if (!do_gates) continue;
                    float x0 = __shfl_xor_sync(0xFFFFFFFFu, c0, 1);
                    float x1 = __shfl_xor_sync(0xFFFFFFFFu, c1, 1);
                    float x2 = __shfl_xor_sync(0xFFFFFFFFu, c2, 1);
                    float x3 = __shfl_xor_sync(0xFFFFFFFFu, c3, 1);
                    int p = tig & 1;
                    int r = rr + (p ? 8 : 0);
                    int j = (fb >> 2) + (tig >> 1);
                    float gi = p ? x2 : c0;
                    float gf = p ? x3 : c1;
                    float gg = p ? c2 : x0;
                    float go = p ? c3 : x1;
                    float4 xa = *(const float4*)&g_xproj[(size_t)r * G4 + 4 * j];
                    float i_ = sigf(gi + xa.x);
                    float f_ = sigf(gf + xa.y);
                    float g_ = tanhf(gg + xa.z);
                    float o_ = sigf(go + xa.w);
                    float cn = f_ * g_c[r * H_ + j] + i_ * g_;   // c fixed (read-only)
                    float h = o_ * tanhf(cn);
                    hout[(size_t)r * H_ + j] = __uint_as_float(tf32r(h));
                } else {
                    if (!do_hw2) continue;
                    int cc = fb + 2 * tig - G4;
                    size_t base = ((size_t)(st - 1) * B_ + rr) * W_;
                    *(float2*)&g_hw2all[base + cc]            = make_float2(c0, c1);
                    *(float2*)&g_hw2all[base + (size_t)8 * W_ + cc] = make_float2(c2, c3);
                }
            }
        }
        gridbar(&g_barD[st], 128);
    }
}

// ---------------- mega attention: grid (256 b, 8 t-tiles), 256 thr ----------------
__global__ __launch_bounds__(256)
void attn_mega(const float* __restrict__ vt, float* __restrict__ out) {
    __shared__ float hw2s[16 * 512];
    __shared__ float sc[16 * 128];
    int b = blockIdx.x, t0 = blockIdx.y * 16;
    int tid = threadIdx.x, lane = tid & 31, w = tid >> 5;

    for (int i = tid * 4; i < 16 * 512; i += 256 * 4) {
        int t = i >> 9, c = i & 511;
        *(float4*)&hw2s[i] = *(const float4*)&g_hw2all[((size_t)(t0 + t) * B_ + b) * W_ + c];
    }
    float4 vv[4];
    #pragma unroll
    for (int j = 0; j < 4; j++) vv[j] = *(const float4*)&vt[j * 128 + lane * 4];
    __syncthreads();

    float4 er[4], ern[4];
    {
        const float* ep = &g_enc_proj[((size_t)w * B_ + b) * W_];
        #pragma unroll
        for (int j = 0; j < 4; j++) er[j] = *(const float4*)&ep[j * 128 + lane * 4];
    }
    for (int si = 0; si < 16; si++) {
        int s = si * 8 + w;
        if (si < 15) {
            const float* ep = &g_enc_proj[((size_t)(s + 8) * B_ + b) * W_];
            #pragma unroll
            for (int j = 0; j < 4; j++) ern[j] = *(const float4*)&ep[j * 128 + lane * 4];
        }
        #pragma unroll 4
        for (int tl = 0; tl < 16; tl++) {
            float a = 0.0f;
            #pragma unroll
            for (int j = 0; j < 4; j++) {
                float4 hv = *(const float4*)&hw2s[tl * 512 + j * 128 + lane * 4];
                a += fast_tanh(er[j].x + hv.x) * vv[j].x;
                a += fast_tanh(er[j].y + hv.y) * vv[j].y;
                a += fast_tanh(er[j].z + hv.z) * vv[j].z;
                a += fast_tanh(er[j].w + hv.w) * vv[j].w;
            }
            #pragma unroll
            for (int off = 16; off; off >>= 1) a += __shfl_xor_sync(0xFFFFFFFFu, a, off);
            if (lane == 0) sc[tl * 128 + s] = a;
        }
        #pragma unroll
        for (int j = 0; j < 4; j++) er[j] = ern[j];
    }
    __syncthreads();

    for (int tl = w; tl < 16; tl += 8) {
        float4 v = *(const float4*)&sc[tl * 128 + lane * 4];
        float m = fmaxf(fmaxf(v.x, v.y), fmaxf(v.z, v.w));
        #pragma unroll
        for (int off = 16; off; off >>= 1) m = fmaxf(m, __shfl_xor_sync(0xFFFFFFFFu, m, off));
        float e = __expf(v.x - m) + __expf(v.y - m) + __expf(v.z - m) + __expf(v.w - m);
        #pragma unroll
        for (int off = 16; off; off >>= 1) e += __shfl_xor_sync(0xFFFFFFFFu, e, off);
        float L = m + logf(e);
        float4 o = make_float4(v.x - L, v.y - L, v.z - L, v.w - L);
        *(float4*)&out[((size_t)b * S_ + (t0 + tl)) * S_ + lane * 4] = o;
    }
}

// ---------------- launch ----------------
extern "C" void kernel_launch(void* const* d_in, const int* in_sizes, int n_in,
                              void* d_out, int out_size) {
    const float* x        = (const float*)d_in[0];
    const float* dec_in   = (const float*)d_in[1];
    const float* W_ih_enc = (const float*)d_in[2];
    const float* W_hh_enc = (const float*)d_in[3];
    const float* b_ih_enc = (const float*)d_in[4];
    const float* b_hh_enc = (const float*)d_in[5];
    const float* W_ih_dec = (const float*)d_in[6];
    const float* W_hh_dec = (const float*)d_in[7];
    const float* b_ih_dec = (const float*)d_in[8];
    const float* b_hh_dec = (const float*)d_in[9];
    const float* W1       = (const float*)d_in[10];
    const float* W2       = (const float*)d_in[11];
    const float* vt       = (const float*)d_in[12];
    float* out = (float*)d_out;

    float *p_encouts, *p_encproj, *p_Wih, *p_W1r, *p_xall, *p_xproj, *p_bce,
          *p_Wihdec, *p_bdec;
    cudaGetSymbolAddress((void**)&p_encouts, g_enc_outs);
    cudaGetSymbolAddress((void**)&p_encproj, g_enc_proj);
    cudaGetSymbolAddress((void**)&p_Wih,     g_Wih_p);
    cudaGetSymbolAddress((void**)&p_W1r,     g_W1r);
    cudaGetSymbolAddress((void**)&p_xall,    g_xall);
    cudaGetSymbolAddress((void**)&p_xproj,   g_xproj);
    cudaGetSymbolAddress((void**)&p_bce,     g_bc_enc);
    cudaGetSymbolAddress((void**)&p_Wihdec,  g_Wihdec_p);
    cudaGetSymbolAddress((void**)&p_bdec,    g_bdec);

    const int ENC_SMEM = (64 * BSTRIDE + 2 * 64 * 36) * 4;          // 150,528
    const int DEC_SMEM = (NTILE_DEC * BSTRIDE + 2 * 64 * 36) * 4;   // 183,552
    cudaFuncSetAttribute(enc_persist, cudaFuncAttributeMaxDynamicSharedMemorySize, ENC_SMEM);
    cudaFuncSetAttribute(dec_chain,   cudaFuncAttributeMaxDynamicSharedMemorySize, DEC_SMEM);

    // prep
    k_prep_enc<<<G4, H_>>>(W_ih_enc, W_hh_enc, b_ih_enc, b_hh_enc);
    k_prep_dec<<<NDEC, H_>>>(W_hh_dec, W2, W_ih_dec, b_ih_dec, b_hh_dec);
    k_prep_W1<<<W_, H_>>>(W1);
    k_zero<<<(B_ * H_ + 255) / 256, 256>>>();

    // xall = x @ W_ih_enc^T + bias  (rows b*S+t)
    gemm_tf32<1><<<dim3(G4 / 64, (B_ * S_) / 64), 128>>>(x, IN_, p_Wih, IN_,
                                                         p_xall, G4, IN_, p_bce);
    // xproj = dec_in @ W_ih_dec^T + bias
    gemm_tf32<1><<<dim3(G4 / 64, B_ / 64), 128>>>(dec_in, IN_, p_Wihdec, IN_,
                                                  p_xproj, G4, IN_, p_bdec);

    // persistent encoder (h_last -> g_hA, c_last -> g_c)
    enc_persist<<<128, 128, ENC_SMEM>>>();

    // enc_proj = enc_outs @ W1^T
    gemm_tf32<0><<<dim3(W_ / 64, (S_ * B_) / 64), 128>>>(p_encouts, H_, p_W1r, H_,
                                                         p_encproj, W_, H_, nullptr);

    // persistent decoder hidden chain -> g_hw2all
    dec_chain<<<128, 128, DEC_SMEM>>>();

    // mega attention + log_softmax
    attn_mega<<<dim3(B_, 8), 256>>>(vt, out);

    (void)in_sizes; (void)n_in; (void)out_size;
}

// round 6
// speedup vs baseline: 2.9945x; 1.2872x over previous
#include <cuda_runtime.h>
#include <cuda_bf16.h>
#include <cstdint>
#include <cstddef>

#define B_ 256
#define S_ 128
#define IN_ 64
#define H_ 512
#define W_ 512
#define G4 2048
#define NDEC 2560

typedef __nv_bfloat16 bf16;

// ---------------- device globals ----------------
__device__ __align__(16) bf16 g_Whhb[G4 * H_];      // quad-permuted W_hh_enc
__device__ __align__(16) bf16 g_Wihb[G4 * IN_];
__device__ float g_bce[G4];
__device__ __align__(16) bf16 g_Mdecb[(size_t)NDEC * H_]; // permuted W_hh_dec | W2
__device__ __align__(16) bf16 g_Wihdb[G4 * IN_];
__device__ float g_bd[G4];
__device__ __align__(16) bf16 g_W1b[W_ * H_];
__device__ float g_xall[(size_t)B_ * S_ * G4];      // rows b*S+t
__device__ float g_xproj[B_ * G4];
__device__ float g_c[B_ * H_];
__device__ __align__(16) bf16 g_hA[B_ * H_];
__device__ __align__(16) bf16 g_hB[B_ * H_];
__device__ __align__(16) bf16 g_hd0[B_ * H_];
__device__ __align__(16) bf16 g_hd1[B_ * H_];
__device__ __align__(16) bf16 g_encouts[(size_t)S_ * B_ * H_];  // [t][b][h]
__device__ float g_encproj[(size_t)S_ * B_ * W_];
__device__ float g_hw2all[(size_t)S_ * B_ * W_];
__device__ volatile unsigned g_barE[S_];
__device__ volatile unsigned g_barD[S_ + 2];

// ---------------- helpers ----------------
__device__ __forceinline__ float sigf(float x) { return 1.0f / (1.0f + __expf(-x)); }
__device__ __forceinline__ float fast_tanh(float x) {
    float y; asm("tanh.approx.f32 %0, %1;" : "=f"(y) : "f"(x)); return y;
}
__device__ __forceinline__ uint4 ldcg4u(const void* p) {
    uint4 v;
    asm volatile("ld.global.cg.v4.u32 {%0,%1,%2,%3}, [%4];"
        : "=r"(v.x), "=r"(v.y), "=r"(v.z), "=r"(v.w) : "l"(p));
    return v;
}
__device__ __forceinline__ void gridbar(volatile unsigned* slot, unsigned n) {
    __syncthreads();
    if (threadIdx.x == 0) {
        __threadfence();
        atomicAdd((unsigned*)slot, 1u);
        while (*slot < n) { asm volatile("nanosleep.u32 64;"); }
        __threadfence();
    }
    __syncthreads();
}
__device__ __forceinline__ void mma16(float* d, const uint32_t* a, const uint32_t* b) {
    asm volatile("mma.sync.aligned.m16n8k16.row.col.f32.bf16.bf16.f32 "
        "{%0,%1,%2,%3}, {%4,%5,%6,%7}, {%8,%9}, {%0,%1,%2,%3};"
        : "+f"(d[0]), "+f"(d[1]), "+f"(d[2]), "+f"(d[3])
        : "r"(a[0]), "r"(a[1]), "r"(a[2]), "r"(a[3]), "r"(b[0]), "r"(b[1]));
}
// XOR-swizzled 16B-chunk smem layout (conflict-free fragment LDS)
__device__ __forceinline__ void st16(char* base, int row, int cc, int rowbytes, uint4 v) {
    *(uint4*)(base + row * rowbytes + ((cc ^ (row & 7)) << 4)) = v;
}
__device__ __forceinline__ uint32_t frag32(const char* base, int row, int kcol, int rowbytes) {
    int byte = kcol * 2;
    return *(const uint32_t*)(base + row * rowbytes +
                              ((((byte >> 4) ^ (row & 7)) << 4) | (byte & 15)));
}

// ---------------- prep ----------------
__global__ void k_prep_enc(const float* __restrict__ Wih, const float* __restrict__ Whh,
                           const float* __restrict__ bih, const float* __restrict__ bhh) {
    int q = blockIdx.x, k = threadIdx.x;
    int r = (q & 3) * H_ + (q >> 2);
    g_Whhb[q * H_ + k] = __float2bfloat16_rn(Whh[r * H_ + k]);
    if (k < IN_) g_Wihb[q * IN_ + k] = __float2bfloat16_rn(Wih[r * IN_ + k]);
    if (k == 0) g_bce[q] = bih[r] + bhh[r];
}
__global__ void k_prep_dec(const float* __restrict__ Whh, const float* __restrict__ W2,
                           const float* __restrict__ Wih,
                           const float* __restrict__ bih, const float* __restrict__ bhh) {
    int q = blockIdx.x, k = threadIdx.x;
    if (q < G4) {
        int r = (q & 3) * H_ + (q >> 2);
        g_Mdecb[(size_t)q * H_ + k] = __float2bfloat16_rn(Whh[r * H_ + k]);
        if (k < IN_) g_Wihdb[q * IN_ + k] = __float2bfloat16_rn(Wih[r * IN_ + k]);
        if (k == 0) g_bd[q] = bih[r] + bhh[r];
    } else {
        g_Mdecb[(size_t)q * H_ + k] = __float2bfloat16_rn(W2[(q - G4) * H_ + k]);
    }
}
__global__ void k_prep_W1(const float* __restrict__ W1) {
    int n = blockIdx.x, k = threadIdx.x;
    g_W1b[n * H_ + k] = __float2bfloat16_rn(W1[n * H_ + k]);
}
__global__ void k_zero() {
    int i = blockIdx.x * blockDim.x + threadIdx.x;
    if (i < B_ * H_) g_hA[i] = __float2bfloat16_rn(0.0f);
    if (i < S_)      g_barE[i] = 0u;
    if (i < S_ + 2)  g_barD[i] = 0u;
}

// ---------------- generic bf16 tensor GEMM: C[M,N]=A[M,K]@Bw[N,K]^T ----------------
template<int CONV, int BIAS>
__global__ __launch_bounds__(128)
void gemm_bf(const void* __restrict__ Ain, const bf16* __restrict__ Bw,
             float* __restrict__ C, int K, int ldc, const float* __restrict__ bias)
{
    extern __shared__ char sm[];
    char* Ab = sm;
    char* Bb = sm + (size_t)64 * K * 2;
    const int rb = K * 2;
    int tid = threadIdx.x, lane = tid & 31, warp = tid >> 5;
    int wm = warp >> 1, wn = warp & 1, gid = lane >> 2, tig = lane & 3;
    int m0 = blockIdx.y * 64, n0 = blockIdx.x * 64;
    int cpr = K >> 3;

    for (int i = tid; i < 64 * cpr; i += 128) {
        int row = i / cpr, cc = i % cpr;
        uint4 v;
        if (CONV) {
            const float* ap = (const float*)Ain + (size_t)(m0 + row) * K + cc * 8;
            float4 a0 = *(const float4*)ap, a1 = *(const float4*)(ap + 4);
            __nv_bfloat162 p0 = __float22bfloat162_rn(make_float2(a0.x, a0.y));
            __nv_bfloat162 p1 = __float22bfloat162_rn(make_float2(a0.z, a0.w));
            __nv_bfloat162 p2 = __float22bfloat162_rn(make_float2(a1.x, a1.y));
            __nv_bfloat162 p3 = __float22bfloat162_rn(make_float2(a1.z, a1.w));
            v.x = *(uint32_t*)&p0; v.y = *(uint32_t*)&p1;
            v.z = *(uint32_t*)&p2; v.w = *(uint32_t*)&p3;
        } else {
            v = *(const uint4*)((const char*)Ain + (size_t)(m0 + row) * rb + cc * 16);
        }
        st16(Ab, row, cc, rb, v);
        uint4 w = *(const uint4*)((const char*)Bw + (size_t)(n0 + row) * rb + cc * 16);
        st16(Bb, row, cc, rb, w);
    }
    __syncthreads();

    float acc[2][4][4];
    #pragma unroll
    for (int a = 0; a < 2; a++) for (int b = 0; b < 4; b++) for (int c = 0; c < 4; c++)
        acc[a][b][c] = 0.0f;

    int nks = K >> 4;
    #pragma unroll 4
    for (int ks = 0; ks < nks; ks++) {
        int kc = ks * 16 + tig * 2;
        uint32_t af[2][4], bf[4][2];
        #pragma unroll
        for (int mt = 0; mt < 2; mt++) {
            int r = wm * 32 + mt * 16 + gid;
            af[mt][0] = frag32(Ab, r,     kc,     rb);
            af[mt][1] = frag32(Ab, r + 8, kc,     rb);
            af[mt][2] = frag32(Ab, r,     kc + 8, rb);
            af[mt][3] = frag32(Ab, r + 8, kc + 8, rb);
        }
        #pragma unroll
        for (int nt = 0; nt < 4; nt++) {
            int n = wn * 32 + nt * 8 + gid;
            bf[nt][0] = frag32(Bb, n, kc,     rb);
            bf[nt][1] = frag32(Bb, n, kc + 8, rb);
        }
        #pragma unroll
        for (int mt = 0; mt < 2; mt++)
            #pragma unroll
            for (int nt = 0; nt < 4; nt++) mma16(acc[mt][nt], af[mt], bf[nt]);
    }
    #pragma unroll
    for (int mt = 0; mt < 2; mt++) {
        #pragma unroll
        for (int nt = 0; nt < 4; nt++) {
            float c0 = acc[mt][nt][0], c1 = acc[mt][nt][1];
            float c2 = acc[mt][nt][2], c3 = acc[mt][nt][3];
            int rr = m0 + wm * 32 + mt * 16 + gid;
            int cc = n0 + wn * 32 + nt * 8 + 2 * tig;
            if (BIAS) {
                float b0 = bias[cc], b1 = bias[cc + 1];
                c0 += b0; c1 += b1; c2 += b0; c3 += b1;
            }
            *(float2*)&C[(size_t)rr * ldc + cc]       = make_float2(c0, c1);
            *(float2*)&C[(size_t)(rr + 8) * ldc + cc] = make_float2(c2, c3);
        }
    }
}

// ---------------- persistent chains ----------------
// DEC=0: encoder, grid 128 = 4 m-blocks x 32 n-blocks(64), N=2048
// DEC=1: decoder, grid 128 = 4 m-blocks x 32 n-blocks(80), N=2560 (gates|hw2)
template<int DEC>
__global__ __launch_bounds__(128)
void chain_kernel() {
    extern __shared__ char sm[];
    char* Ab = sm;                 // 64 x 512 bf16 (rb=1024)
    char* Bb = sm + 65536;         // NT x 512 bf16
    const int NT = DEC ? 80 : 64;
    const int NWT = DEC ? 5 : 4;   // n-frags per warp
    int tid = threadIdx.x, lane = tid & 31, warp = tid >> 5;
    int wm = warp >> 1, wn = warp & 1, gid = lane >> 2, tig = lane & 3;
    int bid = blockIdx.x;
    int m0, n0;
    if (DEC) { m0 = (bid & 3) * 64; n0 = (bid >> 2) * 80; }
    else     { m0 = (bid >> 5) * 64; n0 = (bid & 31) * 64; }

    // resident weight tile
    const bf16* Wp = DEC ? g_Mdecb : g_Whhb;
    for (int i = tid; i < NT * 64; i += 128) {
        int row = i >> 6, cc = i & 63;
        uint4 v = *(const uint4*)((const char*)Wp + (size_t)(n0 + row) * 1024 + cc * 16);
        st16(Bb, row, cc, 1024, v);
    }

    // per-thread cell state registers (mapping is step-invariant)
    float creg[2][8];
    #pragma unroll
    for (int mt = 0; mt < 2; mt++)
        #pragma unroll
        for (int nt = 0; nt < NWT; nt++) {
            int fb = n0 + wn * (NWT * 8) + nt * 8;
            if (!DEC) {
                creg[mt][nt] = 0.0f;
            } else if (fb < G4) {
                int p = tig & 1;
                int r = m0 + wm * 32 + mt * 16 + gid + (p ? 8 : 0);
                int j = (fb >> 2) + (tig >> 1);
                creg[mt][nt] = g_c[(size_t)r * H_ + j];
            }
        }
    __syncthreads();

    volatile unsigned* bar = DEC ? g_barD : g_barE;
    int nsteps = DEC ? S_ + 1 : S_;

    for (int st = 0; st < nsteps; st++) {
        const bf16* A;
        bf16* hout;
        if (DEC) {
            A = (st == 0) ? g_hA : ((st & 1) ? g_hd0 : g_hd1);
            hout = (st & 1) ? g_hd1 : g_hd0;
        } else {
            A = (st & 1) ? g_hB : g_hA;
            hout = (st & 1) ? g_hA : g_hB;
        }
        for (int i = tid; i < 64 * 64; i += 128) {
            int row = i >> 6, cc = i & 63;
            uint4 v = ldcg4u((const char*)A + (size_t)(m0 + row) * 1024 + cc * 16);
            st16(Ab, row, cc, 1024, v);
        }
        __syncthreads();

        float acc[2][5][4];
        #pragma unroll
        for (int a = 0; a < 2; a++) for (int b = 0; b < 5; b++) for (int c = 0; c < 4; c++)
            acc[a][b][c] = 0.0f;

        #pragma unroll 4
        for (int ks = 0; ks < 32; ks++) {
            int kc = ks * 16 + tig * 2;
            uint32_t af[2][4], bfr[5][2];
            #pragma unroll
            for (int mt = 0; mt < 2; mt++) {
                int r = wm * 32 + mt * 16 + gid;
                af[mt][0] = frag32(Ab, r,     kc,     1024);
                af[mt][1] = frag32(Ab, r + 8, kc,     1024);
                af[mt][2] = frag32(Ab, r,     kc + 8, 1024);
                af[mt][3] = frag32(Ab, r + 8, kc + 8, 1024);
            }
            #pragma unroll
            for (int nt = 0; nt < NWT; nt++) {
                int n = wn * (NWT * 8) + nt * 8 + gid;
                bfr[nt][0] = frag32(Bb, n, kc,     1024);
                bfr[nt][1] = frag32(Bb, n, kc + 8, 1024);
            }
            #pragma unroll
            for (int mt = 0; mt < 2; mt++)
                #pragma unroll
                for (int nt = 0; nt < NWT; nt++) mma16(acc[mt][nt], af[mt], bfr[nt]);
        }

        bool do_gates = !DEC || (st < S_);
        bool do_hw2   = DEC && (st > 0);
        #pragma unroll
        for (int mt = 0; mt < 2; mt++) {
            #pragma unroll
            for (int nt = 0; nt < NWT; nt++) {
                int fb = n0 + wn * (NWT * 8) + nt * 8;
                float c0 = acc[mt][nt][0], c1 = acc[mt][nt][1];
                float c2 = acc[mt][nt][2], c3 = acc[mt][nt][3];
                int rr = m0 + wm * 32 + mt * 16 + gid;
                if (!DEC || fb < G4) {
                    if (!do_gates) continue;
                    float x0 = __shfl_xor_sync(0xFFFFFFFFu, c0, 1);
                    float x1 = __shfl_xor_sync(0xFFFFFFFFu, c1, 1);
                    float x2 = __shfl_xor_sync(0xFFFFFFFFu, c2, 1);
                    float x3 = __shfl_xor_sync(0xFFFFFFFFu, c3, 1);
                    int p = tig & 1;
                    int r = rr + (p ? 8 : 0);
                    int j = (fb >> 2) + (tig >> 1);
                    float gi = p ? x2 : c0;
                    float gf = p ? x3 : c1;
                    float gg = p ? c2 : x0;
                    float go = p ? c3 : x1;
                    float4 xa;
                    if (DEC) xa = *(const float4*)&g_xproj[(size_t)r * G4 + 4 * j];
                    else     xa = *(const float4*)&g_xall[((size_t)r * S_ + st) * G4 + 4 * j];
                    float i_ = sigf(gi + xa.x);
                    float f_ = sigf(gf + xa.y);
                    float g_ = tanhf(gg + xa.z);
                    float o_ = sigf(go + xa.w);
                    float cn = f_ * creg[mt][nt] + i_ * g_;
                    if (!DEC) creg[mt][nt] = cn;
                    float h = o_ * tanhf(cn);
                    bf16 hb = __float2bfloat16_rn(h);
                    hout[(size_t)r * H_ + j] = hb;
                    if (!DEC) {
                        g_encouts[((size_t)st * B_ + r) * H_ + j] = hb;
                        if (st == S_ - 1) g_c[(size_t)r * H_ + j] = cn;
                    }
                } else {
                    if (!do_hw2) continue;
                    int cc = fb + 2 * tig - G4;
                    size_t base = ((size_t)(st - 1) * B_ + rr) * W_;
                    *(float2*)&g_hw2all[base + cc]                  = make_float2(c0, c1);
                    *(float2*)&g_hw2all[base + (size_t)8 * W_ + cc] = make_float2(c2, c3);
                }
            }
        }
        gridbar(&bar[st], 128);
    }
}

// ---------------- mega attention + log_softmax ----------------
__global__ __launch_bounds__(256)
void attn_mega(const float* __restrict__ vt, float* __restrict__ out) {
    __shared__ float hw2s[16 * 512];
    __shared__ float sc[16 * 128];
    int b = blockIdx.x, t0 = blockIdx.y * 16;
    int tid = threadIdx.x, lane = tid & 31, w = tid >> 5;

    for (int i = tid * 4; i < 16 * 512; i += 256 * 4) {
        int t = i >> 9, c = i & 511;
        *(float4*)&hw2s[i] = *(const float4*)&g_hw2all[((size_t)(t0 + t) * B_ + b) * W_ + c];
    }
    float4 vv[4];
    #pragma unroll
    for (int j = 0; j < 4; j++) vv[j] = *(const float4*)&vt[j * 128 + lane * 4];
    __syncthreads();

    float4 er[4], ern[4];
    {
        const float* ep = &g_encproj[((size_t)w * B_ + b) * W_];
        #pragma unroll
        for (int j = 0; j < 4; j++) er[j] = *(const float4*)&ep[j * 128 + lane * 4];
    }
    for (int si = 0; si < 16; si++) {
        int s = si * 8 + w;
        if (si < 15) {
            const float* ep = &g_encproj[((size_t)(s + 8) * B_ + b) * W_];
            #pragma unroll
            for (int j = 0; j < 4; j++) ern[j] = *(const float4*)&ep[j * 128 + lane * 4];
        }
        #pragma unroll 4
        for (int tl = 0; tl < 16; tl++) {
            float a = 0.0f;
            #pragma unroll
            for (int j = 0; j < 4; j++) {
                float4 hv = *(const float4*)&hw2s[tl * 512 + j * 128 + lane * 4];
                a += fast_tanh(er[j].x + hv.x) * vv[j].x;
                a += fast_tanh(er[j].y + hv.y) * vv[j].y;
                a += fast_tanh(er[j].z + hv.z) * vv[j].z;
                a += fast_tanh(er[j].w + hv.w) * vv[j].w;
            }
            #pragma unroll
            for (int off = 16; off; off >>= 1) a += __shfl_xor_sync(0xFFFFFFFFu, a, off);
            if (lane == 0) sc[tl * 128 + s] = a;
        }
        #pragma unroll
        for (int j = 0; j < 4; j++) er[j] = ern[j];
    }
    __syncthreads();

    for (int tl = w; tl < 16; tl += 8) {
        float4 v = *(const float4*)&sc[tl * 128 + lane * 4];
        float m = fmaxf(fmaxf(v.x, v.y), fmaxf(v.z, v.w));
        #pragma unroll
        for (int off = 16; off; off >>= 1) m = fmaxf(m, __shfl_xor_sync(0xFFFFFFFFu, m, off));
        float e = __expf(v.x - m) + __expf(v.y - m) + __expf(v.z - m) + __expf(v.w - m);
        #pragma unroll
        for (int off = 16; off; off >>= 1) e += __shfl_xor_sync(0xFFFFFFFFu, e, off);
        float L = m + logf(e);
        float4 o = make_float4(v.x - L, v.y - L, v.z - L, v.w - L);
        *(float4*)&out[((size_t)b * S_ + (t0 + tl)) * S_ + lane * 4] = o;
    }
}

// ---------------- launch ----------------
extern "C" void kernel_launch(void* const* d_in, const int* in_sizes, int n_in,
                              void* d_out, int out_size) {
    const float* x        = (const float*)d_in[0];
    const float* dec_in   = (const float*)d_in[1];
    const float* W_ih_enc = (const float*)d_in[2];
    const float* W_hh_enc = (const float*)d_in[3];
    const float* b_ih_enc = (const float*)d_in[4];
    const float* b_hh_enc = (const float*)d_in[5];
    const float* W_ih_dec = (const float*)d_in[6];
    const float* W_hh_dec = (const float*)d_in[7];
    const float* b_ih_dec = (const float*)d_in[8];
    const float* b_hh_dec = (const float*)d_in[9];
    const float* W1       = (const float*)d_in[10];
    const float* W2       = (const float*)d_in[11];
    const float* vt       = (const float*)d_in[12];
    float* out = (float*)d_out;

    void *p_xall, *p_xproj, *p_Wihb, *p_Wihdb, *p_bce, *p_bd,
         *p_encouts, *p_W1b, *p_encproj;
    cudaGetSymbolAddress(&p_xall,    g_xall);
    cudaGetSymbolAddress(&p_xproj,   g_xproj);
    cudaGetSymbolAddress(&p_Wihb,    g_Wihb);
    cudaGetSymbolAddress(&p_Wihdb,   g_Wihdb);
    cudaGetSymbolAddress(&p_bce,     g_bce);
    cudaGetSymbolAddress(&p_bd,      g_bd);
    cudaGetSymbolAddress(&p_encouts, g_encouts);
    cudaGetSymbolAddress(&p_W1b,     g_W1b);
    cudaGetSymbolAddress(&p_encproj, g_encproj);

    const int ENC_SM  = 64 * 1024 + 64 * 1024;   // 131072
    const int DEC_SM  = 64 * 1024 + 80 * 1024;   // 147456
    const int G512_SM = 512 * 256;               // 131072 (A+B, K=512)
    const int G64_SM  = 64 * 256;                // 16384  (K=64)
    cudaFuncSetAttribute(chain_kernel<0>, cudaFuncAttributeMaxDynamicSharedMemorySize, ENC_SM);
    cudaFuncSetAttribute(chain_kernel<1>, cudaFuncAttributeMaxDynamicSharedMemorySize, DEC_SM);
    cudaFuncSetAttribute(gemm_bf<0, 0>, cudaFuncAttributeMaxDynamicSharedMemorySize, G512_SM);
    cudaFuncSetAttribute(gemm_bf<1, 1>, cudaFuncAttributeMaxDynamicSharedMemorySize, G512_SM);

    k_prep_enc<<<G4, H_>>>(W_ih_enc, W_hh_enc, b_ih_enc, b_hh_enc);
    k_prep_dec<<<NDEC, H_>>>(W_hh_dec, W2, W_ih_dec, b_ih_dec, b_hh_dec);
    k_prep_W1<<<W_, H_>>>(W1);
    k_zero<<<(B_ * H_ + 255) / 256, 256>>>();

    // xall = x @ W_ih_enc^T + bias (rows b*S+t)
    gemm_bf<1, 1><<<dim3(G4 / 64, (B_ * S_) / 64), 128, G64_SM>>>(
        x, (const bf16*)p_Wihb, (float*)p_xall, IN_, G4, (const float*)p_bce);

    // persistent encoder (launch #6 → ncu profiles this)
    chain_kernel<0><<<128, 128, ENC_SM>>>();

    // xproj = dec_in @ W_ih_dec^T + bias
    gemm_bf<1, 1><<<dim3(G4 / 64, B_ / 64), 128, G64_SM>>>(
        dec_in, (const bf16*)p_Wihdb, (float*)p_xproj, IN_, G4, (const float*)p_bd);

    // enc_proj = enc_outs @ W1^T
    gemm_bf<0, 0><<<dim3(W_ / 64, (S_ * B_) / 64), 128, G512_SM>>>(
        p_encouts, (const bf16*)p_W1b, (float*)p_encproj, H_, W_, nullptr);

    // persistent decoder chain (gates | hw2)
    chain_kernel<1><<<128, 128, DEC_SM>>>();

    attn_mega<<<dim3(B_, 8), 256>>>(vt, out);

    (void)in_sizes; (void)n_in; (void)out_size;
}

// round 7
// speedup vs baseline: 3.2527x; 1.0862x over previous
#include <cuda_runtime.h>
#include <cuda_bf16.h>
#include <cstdint>
#include <cstddef>

#define B_ 256
#define S_ 128
#define IN_ 64
#define H_ 512
#define W_ 512
#define G4 2048
#define NDEC 2560      // 2048 gate cols + 512 proj cols
#define KC 576         // concat K: 512 (h) + 64 (x)
#define RB 1152        // smem row bytes (576 bf16), 72 x 16B chunks

typedef __nv_bfloat16 bf16;

// ---------------- device globals ----------------
__device__ __align__(16) bf16 g_Menc[(size_t)NDEC * KC]; // [gates(quad-perm): Whh|Wih ; proj: W1|0]
__device__ float g_be[G4];
__device__ __align__(16) bf16 g_Mdec[(size_t)NDEC * KC]; // [gates(quad-perm): Whh|Wih ; proj: W2|0]
__device__ float g_bd[G4];
__device__ float g_c[B_ * H_];
__device__ __align__(16) bf16 g_hA[B_ * H_];
__device__ __align__(16) bf16 g_hB[B_ * H_];
__device__ __align__(16) bf16 g_hd0[B_ * H_];
__device__ __align__(16) bf16 g_hd1[B_ * H_];
__device__ float g_encproj[(size_t)S_ * B_ * W_];  // [s][b][w]
__device__ float g_hw2all[(size_t)S_ * B_ * W_];   // [t][b][w]
__device__ volatile unsigned g_barE[4 * 129];
__device__ volatile unsigned g_barD[4 * 129];

// ---------------- helpers ----------------
__device__ __forceinline__ float sigf(float x) { return 1.0f / (1.0f + __expf(-x)); }
__device__ __forceinline__ float fast_tanh(float x) {
    float y; asm("tanh.approx.f32 %0, %1;" : "=f"(y) : "f"(x)); return y;
}
__device__ __forceinline__ uint4 ldcg4u(const void* p) {
    uint4 v;
    asm volatile("ld.global.cg.v4.u32 {%0,%1,%2,%3}, [%4];"
        : "=r"(v.x), "=r"(v.y), "=r"(v.z), "=r"(v.w) : "l"(p));
    return v;
}
__device__ __forceinline__ void gridbar(volatile unsigned* slot, unsigned n) {
    __syncthreads();
    if (threadIdx.x == 0) {
        __threadfence();
        atomicAdd((unsigned*)slot, 1u);
        while (*slot < n) { asm volatile("nanosleep.u32 32;"); }
        __threadfence();
    }
    __syncthreads();
}
__device__ __forceinline__ void mma16(float* d, const uint32_t* a, const uint32_t* b) {
    asm volatile("mma.sync.aligned.m16n8k16.row.col.f32.bf16.bf16.f32 "
        "{%0,%1,%2,%3}, {%4,%5,%6,%7}, {%8,%9}, {%0,%1,%2,%3};"
        : "+f"(d[0]), "+f"(d[1]), "+f"(d[2]), "+f"(d[3])
        : "r"(a[0]), "r"(a[1]), "r"(a[2]), "r"(a[3]), "r"(b[0]), "r"(b[1]));
}
// XOR-swizzled 16B-chunk smem layout (conflict-free; row stride RB=1152 ≡ 0 mod 128)
__device__ __forceinline__ void st16(char* base, int row, int cc, uint4 v) {
    *(uint4*)(base + row * RB + ((cc ^ (row & 7)) << 4)) = v;
}
__device__ __forceinline__ uint32_t frag32(const char* base, int row, int kcol) {
    int byte = kcol * 2;
    return *(const uint32_t*)(base + row * RB +
                              ((((byte >> 4) ^ (row & 7)) << 4) | (byte & 15)));
}
__device__ __forceinline__ uint4 packbf8(const float* p) {
    float4 a0 = *(const float4*)p, a1 = *(const float4*)(p + 4);
    __nv_bfloat162 p0 = __float22bfloat162_rn(make_float2(a0.x, a0.y));
    __nv_bfloat162 p1 = __float22bfloat162_rn(make_float2(a0.z, a0.w));
    __nv_bfloat162 p2 = __float22bfloat162_rn(make_float2(a1.x, a1.y));
    __nv_bfloat162 p3 = __float22bfloat162_rn(make_float2(a1.z, a1.w));
    uint4 v;
    v.x = *(uint32_t*)&p0; v.y = *(uint32_t*)&p1;
    v.z = *(uint32_t*)&p2; v.w = *(uint32_t*)&p3;
    return v;
}

// ---------------- prep: build concat weight matrices ----------------
__global__ void k_prep(const float* __restrict__ Wih, const float* __restrict__ Whh,
                       const float* __restrict__ bih, const float* __restrict__ bhh,
                       const float* __restrict__ Wproj, bf16* __restrict__ M,
                       float* __restrict__ bias) {
    int q = blockIdx.x, k = threadIdx.x;   // q<2560, k<576
    float v;
    if (q < G4) {
        int r = (q & 3) * H_ + (q >> 2);   // quad-permuted gate row
        v = (k < H_) ? Whh[(size_t)r * H_ + k] : Wih[(size_t)r * IN_ + (k - H_)];
        if (k == 0) bias[q] = bih[r] + bhh[r];
    } else {
        v = (k < H_) ? Wproj[(size_t)(q - G4) * H_ + k] : 0.0f;
    }
    M[(size_t)q * KC + k] = __float2bfloat16_rn(v);
}
__global__ void k_zero() {
    int i = blockIdx.x * blockDim.x + threadIdx.x;
    if (i < B_ * H_) g_hA[i] = __float2bfloat16_rn(0.0f);
    if (i < 4 * 129) { g_barE[i] = 0u; g_barD[i] = 0u; }
}

// ---------------- persistent chain (DEC=0 encoder, DEC=1 decoder) ----------------
// grid 128 = 4 m-groups x 32 n-blocks(80). 129 steps:
//   gates (cols<2048) at st<128: h_{st} = LSTMcell([h_{st-1}|x], c)
//   proj  (cols>=2048) at st>=1: h_{st-1} @ Wproj^T -> encproj/hw2all[st-1]
template<int DEC>
__global__ __launch_bounds__(128)
void chain_kernel(const float* __restrict__ xg) {
    extern __shared__ char sm[];
    char* Ab = sm;                 // 64 rows x 1152B = 73728
    char* Bb = sm + 64 * RB;       // 80 rows x 1152B = 92160
    int tid = threadIdx.x, lane = tid & 31, warp = tid >> 5;
    int wm = warp >> 1, wn = warp & 1, gid = lane >> 2, tig = lane & 3;
    int mgrp = blockIdx.x & 3, nb = blockIdx.x >> 2;
    int m0 = mgrp * 64, n0 = nb * 80;

    // resident weight tile [80 x 576]
    const bf16* Wp = DEC ? g_Mdec : g_Menc;
    const float* bp = DEC ? g_bd : g_be;
    for (int i = tid; i < 80 * 72; i += 128) {
        int row = i / 72, cc = i % 72;
        uint4 v = *(const uint4*)((const char*)Wp + (size_t)(n0 + row) * RB + cc * 16);
        st16(Bb, row, cc, v);
    }

    // register caches: bias quads + cell state
    float4 bias4[5];
    float creg[2][5];
    #pragma unroll
    for (int nt = 0; nt < 5; nt++) {
        int fb = n0 + wn * 40 + nt * 8;
        if (fb < G4) {
            int j = (fb >> 2) + (tig >> 1);
            bias4[nt] = *(const float4*)&bp[4 * j];
            int p = tig & 1;
            #pragma unroll
            for (int mt = 0; mt < 2; mt++) {
                int r = m0 + wm * 32 + mt * 16 + gid + (p ? 8 : 0);
                creg[mt][nt] = DEC ? g_c[(size_t)r * H_ + j] : 0.0f;
            }
        }
    }
    // decoder: constant x-part (dec_in) loaded once into chunks 64..71
    if (DEC) {
        for (int i = tid; i < 64 * 8; i += 128) {
            int row = i >> 3, c8 = i & 7;
            st16(Ab, row, 64 + c8, packbf8(xg + (size_t)(m0 + row) * IN_ + c8 * 8));
        }
    }
    __syncthreads();

    volatile unsigned* bar = DEC ? g_barD : g_barE;

    for (int st = 0; st < 129; st++) {
        const bf16* A;
        bf16* hout;
        if (DEC) {
            A = (st == 0) ? g_hA : ((st & 1) ? g_hd0 : g_hd1);
            hout = (st & 1) ? g_hd1 : g_hd0;
        } else {
            A = (st & 1) ? g_hB : g_hA;
            hout = (st & 1) ? g_hA : g_hB;
        }
        // h part (chunks 0..63)
        for (int i = tid; i < 64 * 64; i += 128) {
            int row = i >> 6, cc = i & 63;
            uint4 v = ldcg4u((const char*)A + (size_t)(m0 + row) * 1024 + cc * 16);
            st16(Ab, row, cc, v);
        }
        // encoder: x_t part (chunks 64..71)
        if (!DEC) {
            int t = (st < S_) ? st : (S_ - 1);
            for (int i = tid; i < 64 * 8; i += 128) {
                int row = i >> 3, c8 = i & 7;
                st16(Ab, row, 64 + c8,
                     packbf8(xg + ((size_t)(m0 + row) * S_ + t) * IN_ + c8 * 8));
            }
        }
        __syncthreads();

        float acc[2][5][4];
        #pragma unroll
        for (int a = 0; a < 2; a++) for (int b = 0; b < 5; b++) for (int c = 0; c < 4; c++)
            acc[a][b][c] = 0.0f;

        #pragma unroll 4
        for (int ks = 0; ks < 36; ks++) {
            int kc = ks * 16 + tig * 2;
            uint32_t af[2][4], bfr[5][2];
            #pragma unroll
            for (int mt = 0; mt < 2; mt++) {
                int r = wm * 32 + mt * 16 + gid;
                af[mt][0] = frag32(Ab, r,     kc);
                af[mt][1] = frag32(Ab, r + 8, kc);
                af[mt][2] = frag32(Ab, r,     kc + 8);
                af[mt][3] = frag32(Ab, r + 8, kc + 8);
            }
            #pragma unroll
            for (int nt = 0; nt < 5; nt++) {
                int n = wn * 40 + nt * 8 + gid;
                bfr[nt][0] = frag32(Bb, n, kc);
                bfr[nt][1] = frag32(Bb, n, kc + 8);
            }
            #pragma unroll
            for (int mt = 0; mt < 2; mt++)
                #pragma unroll
                for (int nt = 0; nt < 5; nt++) mma16(acc[mt][nt], af[mt], bfr[nt]);
        }

        // epilogue
        #pragma unroll
        for (int mt = 0; mt < 2; mt++) {
            #pragma unroll
            for (int nt = 0; nt < 5; nt++) {
                int fb = n0 + wn * 40 + nt * 8;     // warp-uniform
                float c0 = acc[mt][nt][0], c1 = acc[mt][nt][1];
                float c2 = acc[mt][nt][2], c3 = acc[mt][nt][3];
                int rr = m0 + wm * 32 + mt * 16 + gid;
                if (fb < G4) {
                    if (st >= S_) continue;
                    float x0 = __shfl_xor_sync(0xFFFFFFFFu, c0, 1);
                    float x1 = __shfl_xor_sync(0xFFFFFFFFu, c1, 1);
                    float x2 = __shfl_xor_sync(0xFFFFFFFFu, c2, 1);
                    float x3 = __shfl_xor_sync(0xFFFFFFFFu, c3, 1);
                    int p = tig & 1;
                    int r = rr + (p ? 8 : 0);
                    int j = (fb >> 2) + (tig >> 1);
                    float gi = p ? x2 : c0;
                    float gf = p ? x3 : c1;
                    float gg = p ? c2 : x0;
                    float go = p ? c3 : x1;
                    float4 xa = bias4[nt];
                    float i_ = sigf(gi + xa.x);
                    float f_ = sigf(gf + xa.y);
                    float g_ = tanhf(gg + xa.z);
                    float o_ = sigf(go + xa.w);
                    float cn = f_ * creg[mt][nt] + i_ * g_;   // DEC: c fixed at c_last
                    if (!DEC) {
                        creg[mt][nt] = cn;
                        if (st == S_ - 1) g_c[(size_t)r * H_ + j] = cn;
                    }
                    hout[(size_t)r * H_ + j] = __float2bfloat16_rn(o_ * tanhf(cn));
                } else {
                    if (st == 0) continue;
                    int cc = fb + 2 * tig - G4;
                    float* dst = DEC ? g_hw2all : g_encproj;
                    size_t base = ((size_t)(st - 1) * B_ + rr) * W_;
                    *(float2*)&dst[base + cc]                  = make_float2(c0, c1);
                    *(float2*)&dst[base + (size_t)8 * W_ + cc] = make_float2(c2, c3);
                }
            }
        }
        if (st < 128) gridbar(&bar[st * 4 + mgrp], 32);
    }
}

// ---------------- mega attention + log_softmax ----------------
__global__ __launch_bounds__(256)
void attn_mega(const float* __restrict__ vt, float* __restrict__ out) {
    __shared__ float hw2s[16 * 512];
    __shared__ float sc[16 * 128];
    int b = blockIdx.x, t0 = blockIdx.y * 16;
    int tid = threadIdx.x, lane = tid & 31, w = tid >> 5;

    for (int i = tid * 4; i < 16 * 512; i += 256 * 4) {
        int t = i >> 9, c = i & 511;
        *(float4*)&hw2s[i] = *(const float4*)&g_hw2all[((size_t)(t0 + t) * B_ + b) * W_ + c];
    }
    float4 vv[4];
    #pragma unroll
    for (int j = 0; j < 4; j++) vv[j] = *(const float4*)&vt[j * 128 + lane * 4];
    __syncthreads();

    float4 er[4], ern[4];
    {
        const float* ep = &g_encproj[((size_t)w * B_ + b) * W_];
        #pragma unroll
        for (int j = 0; j < 4; j++) er[j] = *(const float4*)&ep[j * 128 + lane * 4];
    }
    for (int si = 0; si < 16; si++) {
        int s = si * 8 + w;
        if (si < 15) {
            const float* ep = &g_encproj[((size_t)(s + 8) * B_ + b) * W_];
            #pragma unroll
            for (int j = 0; j < 4; j++) ern[j] = *(const float4*)&ep[j * 128 + lane * 4];
        }
        #pragma unroll 4
        for (int tl = 0; tl < 16; tl++) {
            float a = 0.0f;
            #pragma unroll
            for (int j = 0; j < 4; j++) {
                float4 hv = *(const float4*)&hw2s[tl * 512 + j * 128 + lane * 4];
                a += fast_tanh(er[j].x + hv.x) * vv[j].x;
                a += fast_tanh(er[j].y + hv.y) * vv[j].y;
                a += fast_tanh(er[j].z + hv.z) * vv[j].z;
                a += fast_tanh(er[j].w + hv.w) * vv[j].w;
            }
            #pragma unroll
            for (int off = 16; off; off >>= 1) a += __shfl_xor_sync(0xFFFFFFFFu, a, off);
            if (lane == 0) sc[tl * 128 + s] = a;
        }
        #pragma unroll
        for (int j = 0; j < 4; j++) er[j] = ern[j];
    }
    __syncthreads();

    for (int tl = w; tl < 16; tl += 8) {
        float4 v = *(const float4*)&sc[tl * 128 + lane * 4];
        float m = fmaxf(fmaxf(v.x, v.y), fmaxf(v.z, v.w));
        #pragma unroll
        for (int off = 16; off; off >>= 1) m = fmaxf(m, __shfl_xor_sync(0xFFFFFFFFu, m, off));
        float e = __expf(v.x - m) + __expf(v.y - m) + __expf(v.z - m) + __expf(v.w - m);
        #pragma unroll
        for (int off = 16; off; off >>= 1) e += __shfl_xor_sync(0xFFFFFFFFu, e, off);
        float L = m + logf(e);
        float4 o = make_float4(v.x - L, v.y - L, v.z - L, v.w - L);
        *(float4*)&out[((size_t)b * S_ + (t0 + tl)) * S_ + lane * 4] = o;
    }
}

// ---------------- launch ----------------
extern "C" void kernel_launch(void* const* d_in, const int* in_sizes, int n_in,
                              void* d_out, int out_size) {
    const float* x        = (const float*)d_in[0];
    const float* dec_in   = (const float*)d_in[1];
    const float* W_ih_enc = (const float*)d_in[2];
    const float* W_hh_enc = (const float*)d_in[3];
    const float* b_ih_enc = (const float*)d_in[4];
    const float* b_hh_enc = (const float*)d_in[5];
    const float* W_ih_dec = (const float*)d_in[6];
    const float* W_hh_dec = (const float*)d_in[7];
    const float* b_ih_dec = (const float*)d_in[8];
    const float* b_hh_dec = (const float*)d_in[9];
    const float* W1       = (const float*)d_in[10];
    const float* W2       = (const float*)d_in[11];
    const float* vt       = (const float*)d_in[12];
    float* out = (float*)d_out;

    void *p_Menc, *p_Mdec, *p_be, *p_bd;
    cudaGetSymbolAddress(&p_Menc, g_Menc);
    cudaGetSymbolAddress(&p_Mdec, g_Mdec);
    cudaGetSymbolAddress(&p_be,   g_be);
    cudaGetSymbolAddress(&p_bd,   g_bd);

    const int CHAIN_SM = 64 * RB + 80 * RB;   // 165,888
    cudaFuncSetAttribute(chain_kernel<0>, cudaFuncAttributeMaxDynamicSharedMemorySize, CHAIN_SM);
    cudaFuncSetAttribute(chain_kernel<1>, cudaFuncAttributeMaxDynamicSharedMemorySize, CHAIN_SM);

    k_prep<<<NDEC, KC>>>(W_ih_enc, W_hh_enc, b_ih_enc, b_hh_enc, W1,
                         (bf16*)p_Menc, (float*)p_be);
    k_prep<<<NDEC, KC>>>(W_ih_dec, W_hh_dec, b_ih_dec, b_hh_dec, W2,
                         (bf16*)p_Mdec, (float*)p_bd);
    k_zero<<<(B_ * H_ + 255) / 256, 256>>>();

    chain_kernel<0><<<128, 128, CHAIN_SM>>>(x);        // encoder + enc_proj
    chain_kernel<1><<<128, 128, CHAIN_SM>>>(dec_in);   // decoder + hw2

    attn_mega<<<dim3(B_, 8), 256>>>(vt, out);

    (void)in_sizes; (void)n_in; (void)out_size;
}

// round 8
// speedup vs baseline: 4.3611x; 1.3408x over previous
#include <cuda_runtime.h>
#include <cuda_bf16.h>
#include <cstdint>
#include <cstddef>

#define B_ 256
#define S_ 128
#define IN_ 64
#define H_ 512
#define W_ 512
#define G4 2048
#define NDEC 2560      // 2048 gate cols + 512 proj cols
#define KC 576         // concat K: 512 (h) + 64 (x)
#define RB 1152        // smem row bytes (576 bf16), 72 x 16B chunks

typedef __nv_bfloat16 bf16;

// ---------------- device globals ----------------
__device__ __align__(16) bf16 g_Menc[(size_t)NDEC * KC]; // gates(quad-perm): Whh|Wih ; proj: W1|0
__device__ float g_be[G4];
__device__ __align__(16) bf16 g_Mdec[(size_t)NDEC * KC]; // gates(quad-perm): Whh|Wih ; proj: W2|0
__device__ float g_bd[G4];
__device__ float g_c[B_ * H_];
__device__ __align__(16) bf16 g_hA[B_ * H_];
__device__ __align__(16) bf16 g_hB[B_ * H_];
__device__ __align__(16) bf16 g_hd0[B_ * H_];
__device__ __align__(16) bf16 g_hd1[B_ * H_];
__device__ float g_encproj[(size_t)S_ * B_ * W_];  // [s][b][w]
__device__ float g_hw2all[(size_t)S_ * B_ * W_];   // [t][b][w]
__device__ volatile unsigned g_barE[4 * 129];
__device__ volatile unsigned g_barD[4 * 129];

// ---------------- helpers ----------------
__device__ __forceinline__ float sigf(float x) { return 1.0f / (1.0f + __expf(-x)); }
__device__ __forceinline__ float fast_tanh(float x) {
    float y; asm("tanh.approx.f32 %0, %1;" : "=f"(y) : "f"(x)); return y;
}
__device__ __forceinline__ uint4 ldcg4u(const void* p) {
    uint4 v;
    asm volatile("ld.global.cg.v4.u32 {%0,%1,%2,%3}, [%4];"
        : "=r"(v.x), "=r"(v.y), "=r"(v.z), "=r"(v.w) : "l"(p));
    return v;
}
__device__ __forceinline__ void gridbar(volatile unsigned* slot, unsigned n) {
    __syncthreads();
    if (threadIdx.x == 0) {
        __threadfence();
        atomicAdd((unsigned*)slot, 1u);
        while (*slot < n) { asm volatile("nanosleep.u32 32;"); }
        __threadfence();
    }
    __syncthreads();
}
__device__ __forceinline__ void mma16(float* d, const uint32_t* a, const uint32_t* b) {
    asm volatile("mma.sync.aligned.m16n8k16.row.col.f32.bf16.bf16.f32 "
        "{%0,%1,%2,%3}, {%4,%5,%6,%7}, {%8,%9}, {%0,%1,%2,%3};"
        : "+f"(d[0]), "+f"(d[1]), "+f"(d[2]), "+f"(d[3])
        : "r"(a[0]), "r"(a[1]), "r"(a[2]), "r"(a[3]), "r"(b[0]), "r"(b[1]));
}
// XOR-swizzled 16B-chunk smem layout (conflict-free; RB multiple of 128)
__device__ __forceinline__ void st16(char* base, int row, int cc, uint4 v) {
    *(uint4*)(base + row * RB + ((cc ^ (row & 7)) << 4)) = v;
}
__device__ __forceinline__ uint32_t frag32(const char* base, int row, int kcol) {
    int byte = kcol * 2;
    return *(const uint32_t*)(base + row * RB +
                              ((((byte >> 4) ^ (row & 7)) << 4) | (byte & 15)));
}
__device__ __forceinline__ uint4 packbf8(const float* p) {
    float4 a0 = *(const float4*)p, a1 = *(const float4*)(p + 4);
    __nv_bfloat162 p0 = __float22bfloat162_rn(make_float2(a0.x, a0.y));
    __nv_bfloat162 p1 = __float22bfloat162_rn(make_float2(a0.z, a0.w));
    __nv_bfloat162 p2 = __float22bfloat162_rn(make_float2(a1.x, a1.y));
    __nv_bfloat162 p3 = __float22bfloat162_rn(make_float2(a1.z, a1.w));
    uint4 v;
    v.x = *(uint32_t*)&p0; v.y = *(uint32_t*)&p1;
    v.z = *(uint32_t*)&p2; v.w = *(uint32_t*)&p3;
    return v;
}

// ---------------- prep ----------------
__global__ void k_prep(const float* __restrict__ Wih, const float* __restrict__ Whh,
                       const float* __restrict__ bih, const float* __restrict__ bhh,
                       const float* __restrict__ Wproj, bf16* __restrict__ M,
                       float* __restrict__ bias) {
    int q = blockIdx.x, k = threadIdx.x;   // q<2560, k<576
    float v;
    if (q < G4) {
        int r = (q & 3) * H_ + (q >> 2);
        v = (k < H_) ? Whh[(size_t)r * H_ + k] : Wih[(size_t)r * IN_ + (k - H_)];
        if (k == 0) bias[q] = bih[r] + bhh[r];
    } else {
        v = (k < H_) ? Wproj[(size_t)(q - G4) * H_ + k] : 0.0f;
    }
    M[(size_t)q * KC + k] = __float2bfloat16_rn(v);
}
__global__ void k_zero() {
    int i = blockIdx.x * blockDim.x + threadIdx.x;
    if (i < B_ * H_) g_hA[i] = __float2bfloat16_rn(0.0f);
    if (i < 4 * 129) { g_barE[i] = 0u; g_barD[i] = 0u; }
}

// ---------------- persistent chain (DEC=0 encoder, DEC=1 decoder) ----------------
// grid 128 = 4 m-groups x 32 n-blocks(80); 256 threads = 8 warps (4m x 2n), warp tile 16x40
template<int DEC>
__global__ __launch_bounds__(256)
void chain_kernel(const float* __restrict__ xg) {
    extern __shared__ char sm[];
    char* Ab = sm;                 // 64 rows x 1152B
    char* Bb = sm + 64 * RB;       // 80 rows x 1152B
    int tid = threadIdx.x, lane = tid & 31, warp = tid >> 5;
    int wmi = warp >> 1, wn = warp & 1;          // 4 m-warps x 2 n-warps
    int gid = lane >> 2, tig = lane & 3;
    int mgrp = blockIdx.x & 3, nb = blockIdx.x >> 2;
    int m0 = mgrp * 64, n0 = nb * 80;

    // resident weight tile [80 x 576]
    const bf16* Wp = DEC ? g_Mdec : g_Menc;
    const float* bp = DEC ? g_bd : g_be;
    for (int i = tid; i < 80 * 72; i += 256) {
        int row = i / 72, cc = i % 72;
        uint4 v = *(const uint4*)((const char*)Wp + (size_t)(n0 + row) * RB + cc * 16);
        st16(Bb, row, cc, v);
    }

    // register caches: bias quads + cell state (per-thread mapping is step-invariant)
    float4 bias4[5];
    float creg[5];
    #pragma unroll
    for (int nt = 0; nt < 5; nt++) {
        int fb = n0 + wn * 40 + nt * 8;
        if (fb < G4) {
            int j = (fb >> 2) + (tig >> 1);
            bias4[nt] = *(const float4*)&bp[4 * j];
            int p = tig & 1;
            int r = m0 + wmi * 16 + gid + (p ? 8 : 0);
            creg[nt] = DEC ? g_c[(size_t)r * H_ + j] : 0.0f;
        }
    }
    // decoder: constant x-part (dec_in) loaded once (chunks 64..71)
    if (DEC) {
        for (int i = tid; i < 64 * 8; i += 256) {
            int row = i >> 3, c8 = i & 7;
            st16(Ab, row, 64 + c8, packbf8(xg + (size_t)(m0 + row) * IN_ + c8 * 8));
        }
    }
    __syncthreads();

    volatile unsigned* bar = DEC ? g_barD : g_barE;

    for (int st = 0; st < 129; st++) {
        const bf16* A;
        bf16* hout;
        if (DEC) {
            A = (st == 0) ? g_hA : ((st & 1) ? g_hd0 : g_hd1);
            hout = (st & 1) ? g_hd1 : g_hd0;
        } else {
            A = (st & 1) ? g_hB : g_hA;
            hout = (st & 1) ? g_hA : g_hB;
        }
        // h part (chunks 0..63)
        for (int i = tid; i < 64 * 64; i += 256) {
            int row = i >> 6, cc = i & 63;
            uint4 v = ldcg4u((const char*)A + (size_t)(m0 + row) * 1024 + cc * 16);
            st16(Ab, row, cc, v);
        }
        // encoder: x_t part (chunks 64..71)
        if (!DEC) {
            int t = (st < S_) ? st : (S_ - 1);
            for (int i = tid; i < 64 * 8; i += 256) {
                int row = i >> 3, c8 = i & 7;
                st16(Ab, row, 64 + c8,
                     packbf8(xg + ((size_t)(m0 + row) * S_ + t) * IN_ + c8 * 8));
            }
        }
        __syncthreads();

        float acc[5][4];
        #pragma unroll
        for (int b = 0; b < 5; b++)
            #pragma unroll
            for (int c = 0; c < 4; c++) acc[b][c] = 0.0f;

        int rA = wmi * 16 + gid;
        #pragma unroll 4
        for (int ks = 0; ks < 36; ks++) {
            int kc = ks * 16 + tig * 2;
            uint32_t af[4], bfr[5][2];
            af[0] = frag32(Ab, rA,     kc);
            af[1] = frag32(Ab, rA + 8, kc);
            af[2] = frag32(Ab, rA,     kc + 8);
            af[3] = frag32(Ab, rA + 8, kc + 8);
            #pragma unroll
            for (int nt = 0; nt < 5; nt++) {
                int n = wn * 40 + nt * 8 + gid;
                bfr[nt][0] = frag32(Bb, n, kc);
                bfr[nt][1] = frag32(Bb, n, kc + 8);
            }
            #pragma unroll
            for (int nt = 0; nt < 5; nt++) mma16(acc[nt], af, bfr[nt]);
        }

        // epilogue
        #pragma unroll
        for (int nt = 0; nt < 5; nt++) {
            int fb = n0 + wn * 40 + nt * 8;     // warp-uniform
            float c0 = acc[nt][0], c1 = acc[nt][1];
            float c2 = acc[nt][2], c3 = acc[nt][3];
            int rr = m0 + wmi * 16 + gid;
            if (fb < G4) {
                if (st >= S_) continue;
                float x0 = __shfl_xor_sync(0xFFFFFFFFu, c0, 1);
                float x1 = __shfl_xor_sync(0xFFFFFFFFu, c1, 1);
                float x2 = __shfl_xor_sync(0xFFFFFFFFu, c2, 1);
                float x3 = __shfl_xor_sync(0xFFFFFFFFu, c3, 1);
                int p = tig & 1;
                int r = rr + (p ? 8 : 0);
                int j = (fb >> 2) + (tig >> 1);
                float gi = p ? x2 : c0;
                float gf = p ? x3 : c1;
                float gg = p ? c2 : x0;
                float go = p ? c3 : x1;
                float4 xa = bias4[nt];
                float i_ = sigf(gi + xa.x);
                float f_ = sigf(gf + xa.y);
                float g_ = tanhf(gg + xa.z);
                float o_ = sigf(go + xa.w);
                float cn = f_ * creg[nt] + i_ * g_;    // DEC: c fixed at c_last
                if (!DEC) {
                    creg[nt] = cn;
                    if (st == S_ - 1) g_c[(size_t)r * H_ + j] = cn;
                }
                hout[(size_t)r * H_ + j] = __float2bfloat16_rn(o_ * tanhf(cn));
            } else {
                if (st == 0) continue;
                int cc = fb + 2 * tig - G4;
                float* dst = DEC ? g_hw2all : g_encproj;
                size_t base = ((size_t)(st - 1) * B_ + rr) * W_;
                *(float2*)&dst[base + cc]                  = make_float2(c0, c1);
                *(float2*)&dst[base + (size_t)8 * W_ + cc] = make_float2(c2, c3);
            }
        }
        if (st < 128) gridbar(&bar[st * 4 + mgrp], 32);
    }
}

// ---------------- mega attention + log_softmax ----------------
__global__ __launch_bounds__(256)
void attn_mega(const float* __restrict__ vt, float* __restrict__ out) {
    __shared__ float hw2s[16 * 512];
    __shared__ float sc[16 * 128];
    int b = blockIdx.x, t0 = blockIdx.y * 16;
    int tid = threadIdx.x, lane = tid & 31, w = tid >> 5;

    for (int i = tid * 4; i < 16 * 512; i += 256 * 4) {
        int t = i >> 9, c = i & 511;
        *(float4*)&hw2s[i] = *(const float4*)&g_hw2all[((size_t)(t0 + t) * B_ + b) * W_ + c];
    }
    float4 vv[4];
    #pragma unroll
    for (int j = 0; j < 4; j++) vv[j] = *(const float4*)&vt[j * 128 + lane * 4];
    __syncthreads();

    float4 er[4], ern[4];
    {
        const float* ep = &g_encproj[((size_t)w * B_ + b) * W_];
        #pragma unroll
        for (int j = 0; j < 4; j++) er[j] = *(const float4*)&ep[j * 128 + lane * 4];
    }
    for (int si = 0; si < 16; si++) {
        int s = si * 8 + w;
        if (si < 15) {
            const float* ep = &g_encproj[((size_t)(s + 8) * B_ + b) * W_];
            #pragma unroll
            for (int j = 0; j < 4; j++) ern[j] = *(const float4*)&ep[j * 128 + lane * 4];
        }
        #pragma unroll 4
        for (int tl = 0; tl < 16; tl++) {
            float a = 0.0f;
            #pragma unroll
            for (int j = 0; j < 4; j++) {
                float4 hv = *(const float4*)&hw2s[tl * 512 + j * 128 + lane * 4];
                a += fast_tanh(er[j].x + hv.x) * vv[j].x;
                a += fast_tanh(er[j].y + hv.y) * vv[j].y;
                a += fast_tanh(er[j].z + hv.z) * vv[j].z;
                a += fast_tanh(er[j].w + hv.w) * vv[j].w;
            }
            #pragma unroll
            for (int off = 16; off; off >>= 1) a += __shfl_xor_sync(0xFFFFFFFFu, a, off);
            if (lane == 0) sc[tl * 128 + s] = a;
        }
        #pragma unroll
        for (int j = 0; j < 4; j++) er[j] = ern[j];
    }
    __syncthreads();

    for (int tl = w; tl < 16; tl += 8) {
        float4 v = *(const float4*)&sc[tl * 128 + lane * 4];
        float m = fmaxf(fmaxf(v.x, v.y), fmaxf(v.z, v.w));
        #pragma unroll
        for (int off = 16; off; off >>= 1) m = fmaxf(m, __shfl_xor_sync(0xFFFFFFFFu, m, off));
        float e = __expf(v.x - m) + __expf(v.y - m) + __expf(v.z - m) + __expf(v.w - m);
        #pragma unroll
        for (int off = 16; off; off >>= 1) e += __shfl_xor_sync(0xFFFFFFFFu, e, off);
        float L = m + logf(e);
        float4 o = make_float4(v.x - L, v.y - L, v.z - L, v.w - L);
        *(float4*)&out[((size_t)b * S_ + (t0 + tl)) * S_ + lane * 4] = o;
    }
}

// ---------------- launch ----------------
extern "C" void kernel_launch(void* const* d_in, const int* in_sizes, int n_in,
                              void* d_out, int out_size) {
    const float* x        = (const float*)d_in[0];
    const float* dec_in   = (const float*)d_in[1];
    const float* W_ih_enc = (const float*)d_in[2];
    const float* W_hh_enc = (const float*)d_in[3];
    const float* b_ih_enc = (const float*)d_in[4];
    const float* b_hh_enc = (const float*)d_in[5];
    const float* W_ih_dec = (const float*)d_in[6];
    const float* W_hh_dec = (const float*)d_in[7];
    const float* b_ih_dec = (const float*)d_in[8];
    const float* b_hh_dec = (const float*)d_in[9];
    const float* W1       = (const float*)d_in[10];
    const float* W2       = (const float*)d_in[11];
    const float* vt       = (const float*)d_in[12];
    float* out = (float*)d_out;

    void *p_Menc, *p_Mdec, *p_be, *p_bd;
    cudaGetSymbolAddress(&p_Menc, g_Menc);
    cudaGetSymbolAddress(&p_Mdec, g_Mdec);
    cudaGetSymbolAddress(&p_be,   g_be);
    cudaGetSymbolAddress(&p_bd,   g_bd);

    const int CHAIN_SM = 64 * RB + 80 * RB;   // 165,888
    cudaFuncSetAttribute(chain_kernel<0>, cudaFuncAttributeMaxDynamicSharedMemorySize, CHAIN_SM);
    cudaFuncSetAttribute(chain_kernel<1>, cudaFuncAttributeMaxDynamicSharedMemorySize, CHAIN_SM);

    k_prep<<<NDEC, KC>>>(W_ih_enc, W_hh_enc, b_ih_enc, b_hh_enc, W1,
                         (bf16*)p_Menc, (float*)p_be);
    k_prep<<<NDEC, KC>>>(W_ih_dec, W_hh_dec, b_ih_dec, b_hh_dec, W2,
                         (bf16*)p_Mdec, (float*)p_bd);
    k_zero<<<(B_ * H_ + 255) / 256, 256>>>();

    chain_kernel<0><<<128, 256, CHAIN_SM>>>(x);        // encoder + enc_proj
    chain_kernel<1><<<128, 256, CHAIN_SM>>>(dec_in);   // decoder + hw2

    attn_mega<<<dim3(B_, 8), 256>>>(vt, out);

    (void)in_sizes; (void)n_in; (void)out_size;
}